// round 2
// baseline (speedup 1.0000x reference)
#include <cuda_runtime.h>
#include <math.h>

#define L 2048
#define CA 256
#define NH 8
#define HD 32
#define NB 4
static const size_t L2 = (size_t)L * L;

// ---------------- scratch (device globals; no allocation allowed) ----------------
__device__ float g_consts[4];           // c_in, c_skip, c_out, c_noise
__device__ float g_hidden[1024];
__device__ float g_tc[256];
__device__ float g_ss1[NB][512];
__device__ float g_ss2[NB][512];
__device__ float g_h[L * CA];
__device__ float g_h1[L * CA];
__device__ float g_q[L * CA];
__device__ float g_k[L * CA];
__device__ float g_v[L * CA];
__device__ float g_o[L * CA];
__device__ float g_ffn[L * 1024];
__device__ float g_bias[134217728];     // [NB*NH][L][L] = 512 MB

__device__ __forceinline__ float* bufsel(int s) {
    switch (s) {
        case 0: return g_h;
        case 1: return g_h1;
        case 2: return g_q;
        case 3: return g_k;
        case 4: return g_v;
        case 5: return g_o;
        case 6: return g_ffn;
    }
    return nullptr;
}

// ---------------- packed f32x2 helpers (FFMA2: 2x fp32 FMA throughput) ----------------
typedef unsigned long long f32x2;

__device__ __forceinline__ f32x2 pack2(float lo, float hi) {
    f32x2 r;
    asm("mov.b64 %0, {%1, %2};" : "=l"(r) : "f"(lo), "f"(hi));
    return r;
}
__device__ __forceinline__ void unpack2(f32x2 v, float& a, float& b) {
    asm("mov.b64 {%0, %1}, %2;" : "=f"(a), "=f"(b) : "l"(v));
}
__device__ __forceinline__ void fma2(f32x2& d, f32x2 a, f32x2 b) {
    asm("fma.rn.f32x2 %0, %1, %2, %3;" : "=l"(d) : "l"(a), "l"(b), "l"(d));
}

__device__ __forceinline__ float gelu_exact(float x) {
    return 0.5f * x * (1.0f + erff(x * 0.7071067811865475f));
}

// ---------------- tiny setup kernels ----------------
__global__ void k_consts(const float* sigma) {
    float s = sigma[0];
    float sd2 = 256.0f;               // 16^2
    float s2 = s * s + sd2;
    g_consts[0] = rsqrtf(s2);         // c_in
    g_consts[1] = sd2 / s2;           // c_skip
    g_consts[2] = s * 16.0f * rsqrtf(s2);  // c_out
    g_consts[3] = 0.25f * logf(s + 1e-8f); // c_noise
}

// temb -> hidden = gelu(temb @ W1^T + b1)   (1 block, 1024 threads)
__global__ void k_temb(const float* __restrict__ W1, const float* __restrict__ b1) {
    __shared__ float temb[256];
    int t = threadIdx.x;
    float cn = g_consts[3];
    if (t < 256) {
        int j = t & 127;
        float f = expf(-logf(10000.0f) * (float)j / 128.0f);
        float a = cn * f;
        temb[t] = (t < 128) ? cosf(a) : sinf(a);
    }
    __syncthreads();
    const float* w = W1 + (size_t)t * 256;
    float acc = 0.0f;
    #pragma unroll 8
    for (int c = 0; c < 256; c++) acc += temb[c] * w[c];
    g_hidden[t] = gelu_exact(acc + b1[t]);
}

// tc = hidden @ W2^T + b2   (1 block, 256 threads)
__global__ void k_tc(const float* __restrict__ W2, const float* __restrict__ b2) {
    __shared__ float hid[1024];
    int t = threadIdx.x;
    #pragma unroll
    for (int l = 0; l < 4; l++) hid[t + l * 256] = g_hidden[t + l * 256];
    __syncthreads();
    const float* w = W2 + (size_t)t * 1024;
    float acc = 0.0f;
    #pragma unroll 8
    for (int c = 0; c < 1024; c++) acc += hid[c] * w[c];
    g_tc[t] = acc + b2[t];
}

// ada scale/shift precompute for all blocks, both adaLNs (grid 16 x 256)
__global__ void k_ada(const float* __restrict__ pW1, const float* __restrict__ pb1,
                      const float* __restrict__ pW2, const float* __restrict__ pb2) {
    __shared__ float tcs[256];
    int t = threadIdx.x;
    tcs[t] = g_tc[t];
    __syncthreads();
    int gid = blockIdx.x * 256 + t;   // 0..4095
    int blk = gid >> 10;
    int which = (gid >> 9) & 1;
    int idx = gid & 511;
    const float* W = which ? pW2 : pW1;
    const float* pb = which ? pb2 : pb1;
    const float* w = W + ((size_t)blk * 512 + idx) * 256;
    float acc = 0.0f;
    #pragma unroll 8
    for (int c = 0; c < 256; c++) acc += tcs[c] * w[c];
    float val = acc + pb[blk * 512 + idx];
    if (which) g_ss2[blk][idx] = val; else g_ss1[blk][idx] = val;
}

// ---------------- pair bias: bias[bh][r] = sum_c pair[r][c] * pW[bh][c] ----------------
// grid = L*L/128, block = 128 threads. Tile: 128 rows x 32 cols x K=64.
__global__ void k_pairbias(const float* __restrict__ pair, const float* __restrict__ pW) {
    __shared__ __align__(16) float As[64][130];   // As[c][m]
    __shared__ __align__(16) float Bs[64][36];    // Bs[c][bh]
    size_t r0 = (size_t)blockIdx.x * 128;
    int tid = threadIdx.x;
    const float* Ap = pair + r0 * 64;
    #pragma unroll 8
    for (int l = 0; l < 64; l++) {
        int idx = tid + l * 128;
        As[idx & 63][idx >> 6] = Ap[idx];
    }
    #pragma unroll
    for (int l = 0; l < 16; l++) {
        int idx = tid + l * 128;
        Bs[idx & 63][idx >> 6] = pW[idx];
    }
    __syncthreads();
    int rg = tid & 15;     // row group: rows rg*2 + 32*ii + {0,1}
    int cg = tid >> 4;     // col group: cols cg*4 + j
    f32x2 acc2[4][4];
    #pragma unroll
    for (int i = 0; i < 4; i++)
        #pragma unroll
        for (int j = 0; j < 4; j++) acc2[i][j] = 0ULL;

    #pragma unroll 4
    for (int c = 0; c < 64; c++) {
        f32x2 a2[4];
        #pragma unroll
        for (int ii = 0; ii < 4; ii++)
            a2[ii] = *(const f32x2*)&As[c][rg * 2 + 32 * ii];
        #pragma unroll
        for (int j = 0; j < 4; j++) {
            float b = Bs[c][cg * 4 + j];
            f32x2 bd = pack2(b, b);
            #pragma unroll
            for (int ii = 0; ii < 4; ii++) fma2(acc2[ii][j], a2[ii], bd);
        }
    }
    #pragma unroll
    for (int j = 0; j < 4; j++) {
        int bh = cg * 4 + j;
        float* bp = g_bias + (size_t)bh * L2 + r0 + rg * 2;
        #pragma unroll
        for (int ii = 0; ii < 4; ii++) {
            float lo, hi;
            unpack2(acc2[ii][j], lo, hi);
            *(float2*)(bp + 32 * ii) = make_float2(lo, hi);
        }
    }
}

// ---------------- generic GEMM: C[M,N] = epi(A[M,K] @ W[N,K]^T) ----------------
// BM=BN=64, BK=32, 256 threads. Per-thread 4x4 via f32x2 row-pairs.
#define EPI_BIAS  1
#define EPI_GELU  2
#define EPI_RES   4
#define EPI_COORD 8

template <int EPI>
__global__ void k_gemm(const float* __restrict__ Aext, int a_sel,
                       const float* __restrict__ W,
                       const float* __restrict__ bias,
                       int res_sel, int c_sel, int K, int N,
                       const float* __restrict__ x3,
                       const float* __restrict__ cw3,
                       const float* __restrict__ cb3) {
    __shared__ __align__(16) float As[32][66];
    __shared__ __align__(16) float Bs[32][65];
    const float* A = (a_sel >= 0) ? bufsel(a_sel) : Aext;
    float* C = bufsel(c_sel);
    int m0 = blockIdx.y * 64, n0 = blockIdx.x * 64;
    int tid = threadIdx.x, tx = tid & 15, ty = tid >> 4;

    f32x2 acc2[2][4];
    #pragma unroll
    for (int i = 0; i < 2; i++)
        #pragma unroll
        for (int j = 0; j < 4; j++) acc2[i][j] = 0ULL;

    for (int kt = 0; kt < K; kt += 32) {
        __syncthreads();
        #pragma unroll
        for (int l = 0; l < 8; l++) {
            int idx = tid + l * 256;
            int r = idx >> 5, c = idx & 31;
            As[c][r] = A[(size_t)(m0 + r) * K + kt + c];
            Bs[c][r] = W[(size_t)(n0 + r) * K + kt + c];
        }
        __syncthreads();
        #pragma unroll 8
        for (int k = 0; k < 32; k++) {
            f32x2 a2[2];
            a2[0] = *(const f32x2*)&As[k][ty * 4];
            a2[1] = *(const f32x2*)&As[k][ty * 4 + 2];
            float b0 = Bs[k][tx], b1 = Bs[k][tx + 16];
            float b2v = Bs[k][tx + 32], b3 = Bs[k][tx + 48];
            f32x2 bd0 = pack2(b0, b0), bd1 = pack2(b1, b1);
            f32x2 bd2 = pack2(b2v, b2v), bd3 = pack2(b3, b3);
            fma2(acc2[0][0], a2[0], bd0); fma2(acc2[1][0], a2[1], bd0);
            fma2(acc2[0][1], a2[0], bd1); fma2(acc2[1][1], a2[1], bd1);
            fma2(acc2[0][2], a2[0], bd2); fma2(acc2[1][2], a2[1], bd2);
            fma2(acc2[0][3], a2[0], bd3); fma2(acc2[1][3], a2[1], bd3);
        }
    }
    const float* res = nullptr;
    if (EPI & EPI_RES) res = bufsel(res_sel);
    float cin = (EPI & EPI_COORD) ? g_consts[0] : 0.0f;
    #pragma unroll
    for (int ip = 0; ip < 2; ip++) {
        #pragma unroll
        for (int j = 0; j < 4; j++) {
            float v0, v1;
            unpack2(acc2[ip][j], v0, v1);
            int col = n0 + tx + 16 * j;
            #pragma unroll
            for (int rr = 0; rr < 2; rr++) {
                int row = m0 + ty * 4 + ip * 2 + rr;
                float v = rr ? v1 : v0;
                if (EPI & EPI_BIAS) v += bias[col];
                if (EPI & EPI_COORD) {
                    v += cin * (x3[row * 3 + 0] * cw3[col * 3 + 0] +
                                x3[row * 3 + 1] * cw3[col * 3 + 1] +
                                x3[row * 3 + 2] * cw3[col * 3 + 2]) + cb3[col];
                }
                if (EPI & EPI_GELU) v = gelu_exact(v);
                if (EPI & EPI_RES) v += res[(size_t)row * N + col];
                C[(size_t)row * N + col] = v;
            }
        }
    }
}

// ---------------- adaLN (h -> h1), one block per row ----------------
__global__ void k_adaln(const float* __restrict__ gamma, const float* __restrict__ beta,
                        int b, int which) {
    __shared__ float red[2][8];
    int row = blockIdx.x, t = threadIdx.x;
    int lane = t & 31, wid = t >> 5;
    float x = g_h[(size_t)row * 256 + t];
    float s1 = x, s2 = x * x;
    #pragma unroll
    for (int off = 16; off > 0; off >>= 1) {
        s1 += __shfl_xor_sync(0xffffffffu, s1, off);
        s2 += __shfl_xor_sync(0xffffffffu, s2, off);
    }
    if (lane == 0) { red[0][wid] = s1; red[1][wid] = s2; }
    __syncthreads();
    float S = 0.0f, Q = 0.0f;
    #pragma unroll
    for (int w = 0; w < 8; w++) { S += red[0][w]; Q += red[1][w]; }
    float mu = S * (1.0f / 256.0f);
    float var = Q * (1.0f / 256.0f) - mu * mu;
    float rs = rsqrtf(var + 1e-5f);
    const float* ss = which ? g_ss2[b] : g_ss1[b];
    float scale = ss[t], shift = ss[256 + t];
    g_h1[(size_t)row * 256 + t] =
        ((x - mu) * rs * gamma[t] + beta[t]) * (1.0f + scale) + shift;
}

// ---------------- attention: grid (L/64, NH), 256 threads ----------------
// Unnormalized softmax (logits provably small): o = (sum_j e^S v_j) / (sum_j e^S)
__global__ void k_attn(int b) {
    __shared__ __align__(16) float qs[64][34];
    __shared__ __align__(16) float ks[64][34];
    __shared__ __align__(16) float vs[64][32];
    __shared__ float ps[64][65];

    int it = blockIdx.x, h = blockIdx.y;
    int i0 = it * 64;
    const float* bias = g_bias + (size_t)(b * NH + h) * L2;
    int tid = threadIdx.x;

    #pragma unroll
    for (int l = 0; l < 8; l++) {
        int idx = tid + l * 256;
        int r = idx >> 5, c = idx & 31;
        qs[r][c] = g_q[(size_t)(i0 + r) * 256 + h * 32 + c];
    }
    __syncthreads();

    int iA = tid >> 2, jA0 = (tid & 3) * 16;
    int dg = tid & 3;
    f32x2 qr[16];
    #pragma unroll
    for (int c = 0; c < 16; c++) qr[c] = *(const f32x2*)&qs[iA][2 * c];

    f32x2 o2[4] = {0ULL, 0ULL, 0ULL, 0ULL};
    float lsum = 0.0f;
    const float scale = 0.1767766952966369f;  // 1/sqrt(32)

    for (int jt = 0; jt < 32; jt++) {
        int j0 = jt * 64;
        __syncthreads();
        #pragma unroll
        for (int l = 0; l < 8; l++) {
            int idx = tid + l * 256;
            int r = idx >> 5, c = idx & 31;
            ks[r][c] = g_k[(size_t)(j0 + r) * 256 + h * 32 + c];
            vs[r][c] = g_v[(size_t)(j0 + r) * 256 + h * 32 + c];
        }
        #pragma unroll
        for (int l = 0; l < 16; l++) {
            int idx = tid + l * 256;
            int r = idx >> 6, c = idx & 63;
            ps[r][c] = bias[(size_t)(i0 + r) * L + j0 + c];
        }
        __syncthreads();
        // phase A: S tile + exp, in place over staged bias
        #pragma unroll 2
        for (int jj = 0; jj < 16; jj++) {
            int j = jA0 + jj;
            f32x2 accA = 0ULL, accB = 0ULL;
            const f32x2* kp = (const f32x2*)&ks[j][0];
            #pragma unroll
            for (int c = 0; c < 16; c += 2) {
                fma2(accA, qr[c], kp[c]);
                fma2(accB, qr[c + 1], kp[c + 1]);
            }
            float a0, a1, b0, b1;
            unpack2(accA, a0, a1);
            unpack2(accB, b0, b1);
            float s = (a0 + a1) + (b0 + b1);
            ps[iA][j] = __expf(s * scale + ps[iA][j]);
        }
        __syncthreads();
        // phase B: o += P @ V
        #pragma unroll 4
        for (int j = 0; j < 64; j++) {
            float p = ps[iA][j];
            lsum += p;
            f32x2 pd = pack2(p, p);
            const f32x2* vp = (const f32x2*)&vs[j][dg * 8];
            fma2(o2[0], pd, vp[0]);
            fma2(o2[1], pd, vp[1]);
            fma2(o2[2], pd, vp[2]);
            fma2(o2[3], pd, vp[3]);
        }
    }
    float inv = 1.0f / lsum;
    float* op = g_o + (size_t)(i0 + iA) * 256 + h * 32 + dg * 8;
    #pragma unroll
    for (int q = 0; q < 4; q++) {
        float lo, hi;
        unpack2(o2[q], lo, hi);
        op[2 * q] = lo * inv;
        op[2 * q + 1] = hi * inv;
    }
}

// ---------------- final projection: out = c_skip*x + c_out*(h @ outW^T + out_b) ----------------
__global__ void k_final(const float* __restrict__ x, const float* __restrict__ oW,
                        const float* __restrict__ ob, float* __restrict__ out) {
    int row = blockIdx.x;
    int w = threadIdx.x >> 5, lane = threadIdx.x & 31;
    const float* hr = g_h + (size_t)row * 256;
    const float* wr = oW + w * 256;
    float acc = 0.0f;
    #pragma unroll
    for (int c = lane; c < 256; c += 32) acc += hr[c] * wr[c];
    #pragma unroll
    for (int off = 16; off > 0; off >>= 1)
        acc += __shfl_down_sync(0xffffffffu, acc, off);
    if (lane == 0)
        out[row * 3 + w] = g_consts[1] * x[row * 3 + w] + g_consts[2] * (acc + ob[w]);
}

// ---------------- host launcher ----------------
extern "C" void kernel_launch(void* const* d_in, const int* in_sizes, int n_in,
                              void* d_out, int out_size) {
    const float* x_noisy  = (const float*)d_in[0];
    const float* sigma    = (const float*)d_in[1];
    const float* single   = (const float*)d_in[2];
    const float* pair     = (const float*)d_in[3];
    const float* coord_W  = (const float*)d_in[4];
    const float* coord_b  = (const float*)d_in[5];
    const float* single_W = (const float*)d_in[6];
    const float* single_b = (const float*)d_in[7];
    const float* tmlp_W1  = (const float*)d_in[8];
    const float* tmlp_b1  = (const float*)d_in[9];
    const float* tmlp_W2  = (const float*)d_in[10];
    const float* tmlp_b2  = (const float*)d_in[11];
    const float* ada1_g   = (const float*)d_in[12];
    const float* ada1_b   = (const float*)d_in[13];
    const float* ada1_pW  = (const float*)d_in[14];
    const float* ada1_pb  = (const float*)d_in[15];
    const float* qW       = (const float*)d_in[16];
    const float* kW       = (const float*)d_in[17];
    const float* vW       = (const float*)d_in[18];
    const float* pairW    = (const float*)d_in[19];
    const float* outW     = (const float*)d_in[20];
    const float* outb     = (const float*)d_in[21];
    const float* ada2_g   = (const float*)d_in[22];
    const float* ada2_b   = (const float*)d_in[23];
    const float* ada2_pW  = (const float*)d_in[24];
    const float* ada2_pb  = (const float*)d_in[25];
    const float* ffn_W1   = (const float*)d_in[26];
    const float* ffn_b1   = (const float*)d_in[27];
    const float* ffn_W2   = (const float*)d_in[28];
    const float* ffn_b2   = (const float*)d_in[29];
    const float* out_W    = (const float*)d_in[30];
    const float* out_b    = (const float*)d_in[31];
    float* out = (float*)d_out;

    k_consts<<<1, 1>>>(sigma);
    k_temb<<<1, 1024>>>(tmlp_W1, tmlp_b1);
    k_tc<<<1, 256>>>(tmlp_W2, tmlp_b2);
    k_ada<<<16, 256>>>(ada1_pW, ada1_pb, ada2_pW, ada2_pb);
    k_pairbias<<<(int)(L2 / 128), 128>>>(pair, pairW);

    // h init: single @ single_W^T + single_b + (c_in*x) @ coord_W^T + coord_b
    k_gemm<EPI_BIAS | EPI_COORD><<<dim3(4, 32), 256>>>(
        single, -1, single_W, single_b, -1, 0, 256, 256, x_noisy, coord_W, coord_b);

    for (int b = 0; b < NB; b++) {
        k_adaln<<<L, 256>>>(ada1_g + b * 256, ada1_b + b * 256, b, 0);
        k_gemm<0><<<dim3(4, 32), 256>>>(nullptr, 1, qW + (size_t)b * 65536, nullptr, -1, 2, 256, 256, nullptr, nullptr, nullptr);
        k_gemm<0><<<dim3(4, 32), 256>>>(nullptr, 1, kW + (size_t)b * 65536, nullptr, -1, 3, 256, 256, nullptr, nullptr, nullptr);
        k_gemm<0><<<dim3(4, 32), 256>>>(nullptr, 1, vW + (size_t)b * 65536, nullptr, -1, 4, 256, 256, nullptr, nullptr, nullptr);
        k_attn<<<dim3(32, 8), 256>>>(b);
        // h = h + o @ outW^T + outb
        k_gemm<EPI_BIAS | EPI_RES><<<dim3(4, 32), 256>>>(
            nullptr, 5, outW + (size_t)b * 65536, outb + b * 256, 0, 0, 256, 256, nullptr, nullptr, nullptr);
        k_adaln<<<L, 256>>>(ada2_g + b * 256, ada2_b + b * 256, b, 1);
        // ffn1: gelu(h2 @ W1^T + b1)
        k_gemm<EPI_BIAS | EPI_GELU><<<dim3(16, 32), 256>>>(
            nullptr, 1, ffn_W1 + (size_t)b * 262144, ffn_b1 + b * 1024, -1, 6, 256, 1024, nullptr, nullptr, nullptr);
        // ffn2: h = h + t @ W2^T + b2
        k_gemm<EPI_BIAS | EPI_RES><<<dim3(4, 32), 256>>>(
            nullptr, 6, ffn_W2 + (size_t)b * 262144, ffn_b2 + b * 256, 0, 0, 1024, 256, nullptr, nullptr, nullptr);
    }
    k_final<<<L, 96>>>(x_noisy, out_W, out_b, out);
}

// round 6
// speedup vs baseline: 1.0041x; 1.0041x over previous
#include <cuda_runtime.h>
#include <math.h>

#define L 2048
#define CA 256
#define NH 8
#define HD 32
#define NB 4
static const size_t L2 = (size_t)L * L;

// ---------------- scratch (device globals; no allocation allowed) ----------------
__device__ float g_consts[4];           // c_in, c_skip, c_out, c_noise
__device__ float g_hidden[1024];
__device__ float g_tc[256];
__device__ float g_ss1[NB][512];
__device__ float g_ss2[NB][512];
__device__ float g_h[L * CA];
__device__ float g_h1[L * CA];
__device__ float g_q[L * CA];
__device__ float g_k[L * CA];
__device__ float g_v[L * CA];
__device__ float g_o[L * CA];
__device__ float g_ffn[L * 1024];
__device__ float g_bias[134217728];     // [NB*NH][L][L] = 512 MB

__device__ __forceinline__ float* bufsel(int s) {
    switch (s) {
        case 0: return g_h;
        case 1: return g_h1;
        case 2: return g_q;
        case 3: return g_k;
        case 4: return g_v;
        case 5: return g_o;
        case 6: return g_ffn;
    }
    return nullptr;
}

// ---------------- packed f32x2 helpers (FFMA2: 2x fp32 FMA throughput) ----------------
typedef unsigned long long f32x2;

__device__ __forceinline__ f32x2 pack2(float lo, float hi) {
    f32x2 r;
    asm("mov.b64 %0, {%1, %2};" : "=l"(r) : "f"(lo), "f"(hi));
    return r;
}
__device__ __forceinline__ void unpack2(f32x2 v, float& a, float& b) {
    asm("mov.b64 {%0, %1}, %2;" : "=f"(a), "=f"(b) : "l"(v));
}
__device__ __forceinline__ void fma2(f32x2& d, f32x2 a, f32x2 b) {
    asm("fma.rn.f32x2 %0, %1, %2, %3;" : "=l"(d) : "l"(a), "l"(b), "l"(d));
}

__device__ __forceinline__ float gelu_exact(float x) {
    return 0.5f * x * (1.0f + erff(x * 0.7071067811865475f));
}

// ---------------- tiny setup kernels ----------------
__global__ void k_consts(const float* sigma) {
    float s = sigma[0];
    float sd2 = 256.0f;               // 16^2
    float s2 = s * s + sd2;
    g_consts[0] = rsqrtf(s2);         // c_in
    g_consts[1] = sd2 / s2;           // c_skip
    g_consts[2] = s * 16.0f * rsqrtf(s2);  // c_out
    g_consts[3] = 0.25f * logf(s + 1e-8f); // c_noise
}

// temb -> hidden = gelu(temb @ W1^T + b1)   (1 block, 1024 threads)
__global__ void k_temb(const float* __restrict__ W1, const float* __restrict__ b1) {
    __shared__ float temb[256];
    int t = threadIdx.x;
    float cn = g_consts[3];
    if (t < 256) {
        int j = t & 127;
        float f = expf(-logf(10000.0f) * (float)j / 128.0f);
        float a = cn * f;
        temb[t] = (t < 128) ? cosf(a) : sinf(a);
    }
    __syncthreads();
    const float* w = W1 + (size_t)t * 256;
    float acc = 0.0f;
    #pragma unroll 8
    for (int c = 0; c < 256; c++) acc += temb[c] * w[c];
    g_hidden[t] = gelu_exact(acc + b1[t]);
}

// tc = hidden @ W2^T + b2   (1 block, 256 threads)
__global__ void k_tc(const float* __restrict__ W2, const float* __restrict__ b2) {
    __shared__ float hid[1024];
    int t = threadIdx.x;
    #pragma unroll
    for (int l = 0; l < 4; l++) hid[t + l * 256] = g_hidden[t + l * 256];
    __syncthreads();
    const float* w = W2 + (size_t)t * 1024;
    float acc = 0.0f;
    #pragma unroll 8
    for (int c = 0; c < 1024; c++) acc += hid[c] * w[c];
    g_tc[t] = acc + b2[t];
}

// ada scale/shift precompute for all blocks, both adaLNs (grid 16 x 256)
__global__ void k_ada(const float* __restrict__ pW1, const float* __restrict__ pb1,
                      const float* __restrict__ pW2, const float* __restrict__ pb2) {
    __shared__ float tcs[256];
    int t = threadIdx.x;
    tcs[t] = g_tc[t];
    __syncthreads();
    int gid = blockIdx.x * 256 + t;   // 0..4095
    int blk = gid >> 10;
    int which = (gid >> 9) & 1;
    int idx = gid & 511;
    const float* W = which ? pW2 : pW1;
    const float* pb = which ? pb2 : pb1;
    const float* w = W + ((size_t)blk * 512 + idx) * 256;
    float acc = 0.0f;
    #pragma unroll 8
    for (int c = 0; c < 256; c++) acc += tcs[c] * w[c];
    float val = acc + pb[blk * 512 + idx];
    if (which) g_ss2[blk][idx] = val; else g_ss1[blk][idx] = val;
}

// ---------------- pair bias: bias[bh][r] = sum_c pair[r][c] * pW[bh][c] ----------------
// grid = L*L/128, block = 128 threads. Tile: 128 rows x 32 cols x K=64.
__global__ void k_pairbias(const float* __restrict__ pair, const float* __restrict__ pW) {
    __shared__ __align__(16) float As[64][130];   // As[c][m]
    __shared__ __align__(16) float Bs[64][36];    // Bs[c][bh]
    size_t r0 = (size_t)blockIdx.x * 128;
    int tid = threadIdx.x;
    const float* Ap = pair + r0 * 64;
    #pragma unroll 8
    for (int l = 0; l < 64; l++) {
        int idx = tid + l * 128;
        As[idx & 63][idx >> 6] = Ap[idx];
    }
    #pragma unroll
    for (int l = 0; l < 16; l++) {
        int idx = tid + l * 128;
        Bs[idx & 63][idx >> 6] = pW[idx];
    }
    __syncthreads();
    int rg = tid & 15;     // row group: rows rg*2 + 32*ii + {0,1}
    int cg = tid >> 4;     // col group: cols cg*4 + j
    f32x2 acc2[4][4];
    #pragma unroll
    for (int i = 0; i < 4; i++)
        #pragma unroll
        for (int j = 0; j < 4; j++) acc2[i][j] = 0ULL;

    #pragma unroll 4
    for (int c = 0; c < 64; c++) {
        f32x2 a2[4];
        #pragma unroll
        for (int ii = 0; ii < 4; ii++)
            a2[ii] = *(const f32x2*)&As[c][rg * 2 + 32 * ii];
        #pragma unroll
        for (int j = 0; j < 4; j++) {
            float b = Bs[c][cg * 4 + j];
            f32x2 bd = pack2(b, b);
            #pragma unroll
            for (int ii = 0; ii < 4; ii++) fma2(acc2[ii][j], a2[ii], bd);
        }
    }
    #pragma unroll
    for (int j = 0; j < 4; j++) {
        int bh = cg * 4 + j;
        float* bp = g_bias + (size_t)bh * L2 + r0 + rg * 2;
        #pragma unroll
        for (int ii = 0; ii < 4; ii++) {
            float lo, hi;
            unpack2(acc2[ii][j], lo, hi);
            *(float2*)(bp + 32 * ii) = make_float2(lo, hi);
        }
    }
}

// ---------------- generic GEMM: C[M,N] = epi(A[M,K] @ W[N,K]^T) ----------------
// BM=BN=64, BK=32, 256 threads. Per-thread 4x4 via f32x2 row-pairs.
#define EPI_BIAS  1
#define EPI_GELU  2
#define EPI_RES   4
#define EPI_COORD 8

template <int EPI>
__global__ void k_gemm(const float* __restrict__ Aext, int a_sel,
                       const float* __restrict__ W,
                       const float* __restrict__ bias,
                       int res_sel, int c_sel, int K, int N,
                       const float* __restrict__ x3,
                       const float* __restrict__ cw3,
                       const float* __restrict__ cb3) {
    __shared__ __align__(16) float As[32][66];
    __shared__ __align__(16) float Bs[32][65];
    const float* A = (a_sel >= 0) ? bufsel(a_sel) : Aext;
    float* C = bufsel(c_sel);
    int m0 = blockIdx.y * 64, n0 = blockIdx.x * 64;
    int tid = threadIdx.x, tx = tid & 15, ty = tid >> 4;

    f32x2 acc2[2][4];
    #pragma unroll
    for (int i = 0; i < 2; i++)
        #pragma unroll
        for (int j = 0; j < 4; j++) acc2[i][j] = 0ULL;

    for (int kt = 0; kt < K; kt += 32) {
        __syncthreads();
        #pragma unroll
        for (int l = 0; l < 8; l++) {
            int idx = tid + l * 256;
            int r = idx >> 5, c = idx & 31;
            As[c][r] = A[(size_t)(m0 + r) * K + kt + c];
            Bs[c][r] = W[(size_t)(n0 + r) * K + kt + c];
        }
        __syncthreads();
        #pragma unroll 8
        for (int k = 0; k < 32; k++) {
            f32x2 a2[2];
            a2[0] = *(const f32x2*)&As[k][ty * 4];
            a2[1] = *(const f32x2*)&As[k][ty * 4 + 2];
            float b0 = Bs[k][tx], b1 = Bs[k][tx + 16];
            float b2v = Bs[k][tx + 32], b3 = Bs[k][tx + 48];
            f32x2 bd0 = pack2(b0, b0), bd1 = pack2(b1, b1);
            f32x2 bd2 = pack2(b2v, b2v), bd3 = pack2(b3, b3);
            fma2(acc2[0][0], a2[0], bd0); fma2(acc2[1][0], a2[1], bd0);
            fma2(acc2[0][1], a2[0], bd1); fma2(acc2[1][1], a2[1], bd1);
            fma2(acc2[0][2], a2[0], bd2); fma2(acc2[1][2], a2[1], bd2);
            fma2(acc2[0][3], a2[0], bd3); fma2(acc2[1][3], a2[1], bd3);
        }
    }
    const float* res = nullptr;
    if (EPI & EPI_RES) res = bufsel(res_sel);
    float cin = (EPI & EPI_COORD) ? g_consts[0] : 0.0f;
    #pragma unroll
    for (int ip = 0; ip < 2; ip++) {
        #pragma unroll
        for (int j = 0; j < 4; j++) {
            float v0, v1;
            unpack2(acc2[ip][j], v0, v1);
            int col = n0 + tx + 16 * j;
            #pragma unroll
            for (int rr = 0; rr < 2; rr++) {
                int row = m0 + ty * 4 + ip * 2 + rr;
                float v = rr ? v1 : v0;
                if (EPI & EPI_BIAS) v += bias[col];
                if (EPI & EPI_COORD) {
                    v += cin * (x3[row * 3 + 0] * cw3[col * 3 + 0] +
                                x3[row * 3 + 1] * cw3[col * 3 + 1] +
                                x3[row * 3 + 2] * cw3[col * 3 + 2]) + cb3[col];
                }
                if (EPI & EPI_GELU) v = gelu_exact(v);
                if (EPI & EPI_RES) v += res[(size_t)row * N + col];
                C[(size_t)row * N + col] = v;
            }
        }
    }
}

// ---------------- adaLN (h -> h1), one block per row ----------------
__global__ void k_adaln(const float* __restrict__ gamma, const float* __restrict__ beta,
                        int b, int which) {
    __shared__ float red[2][8];
    int row = blockIdx.x, t = threadIdx.x;
    int lane = t & 31, wid = t >> 5;
    float x = g_h[(size_t)row * 256 + t];
    float s1 = x, s2 = x * x;
    #pragma unroll
    for (int off = 16; off > 0; off >>= 1) {
        s1 += __shfl_xor_sync(0xffffffffu, s1, off);
        s2 += __shfl_xor_sync(0xffffffffu, s2, off);
    }
    if (lane == 0) { red[0][wid] = s1; red[1][wid] = s2; }
    __syncthreads();
    float S = 0.0f, Q = 0.0f;
    #pragma unroll
    for (int w = 0; w < 8; w++) { S += red[0][w]; Q += red[1][w]; }
    float mu = S * (1.0f / 256.0f);
    float var = Q * (1.0f / 256.0f) - mu * mu;
    float rs = rsqrtf(var + 1e-5f);
    const float* ss = which ? g_ss2[b] : g_ss1[b];
    float scale = ss[t], shift = ss[256 + t];
    g_h1[(size_t)row * 256 + t] =
        ((x - mu) * rs * gamma[t] + beta[t]) * (1.0f + scale) + shift;
}

// ---------------- attention: grid (L/64, NH), 256 threads ----------------
// Unnormalized softmax (logits provably small): o = (sum_j e^S v_j) / (sum_j e^S)
__global__ void k_attn(int b) {
    __shared__ __align__(16) float qs[64][34];
    __shared__ __align__(16) float ks[64][34];
    __shared__ __align__(16) float vs[64][32];
    __shared__ float ps[64][65];

    int it = blockIdx.x, h = blockIdx.y;
    int i0 = it * 64;
    const float* bias = g_bias + (size_t)(b * NH + h) * L2;
    int tid = threadIdx.x;

    #pragma unroll
    for (int l = 0; l < 8; l++) {
        int idx = tid + l * 256;
        int r = idx >> 5, c = idx & 31;
        qs[r][c] = g_q[(size_t)(i0 + r) * 256 + h * 32 + c];
    }
    __syncthreads();

    int iA = tid >> 2, jA0 = (tid & 3) * 16;
    int dg = tid & 3;
    f32x2 qr[16];
    #pragma unroll
    for (int c = 0; c < 16; c++) qr[c] = *(const f32x2*)&qs[iA][2 * c];

    f32x2 o2[4] = {0ULL, 0ULL, 0ULL, 0ULL};
    float lsum = 0.0f;
    const float scale = 0.1767766952966369f;  // 1/sqrt(32)

    for (int jt = 0; jt < 32; jt++) {
        int j0 = jt * 64;
        __syncthreads();
        #pragma unroll
        for (int l = 0; l < 8; l++) {
            int idx = tid + l * 256;
            int r = idx >> 5, c = idx & 31;
            ks[r][c] = g_k[(size_t)(j0 + r) * 256 + h * 32 + c];
            vs[r][c] = g_v[(size_t)(j0 + r) * 256 + h * 32 + c];
        }
        #pragma unroll
        for (int l = 0; l < 16; l++) {
            int idx = tid + l * 256;
            int r = idx >> 6, c = idx & 63;
            ps[r][c] = bias[(size_t)(i0 + r) * L + j0 + c];
        }
        __syncthreads();
        // phase A: S tile + exp, in place over staged bias
        #pragma unroll 2
        for (int jj = 0; jj < 16; jj++) {
            int j = jA0 + jj;
            f32x2 accA = 0ULL, accB = 0ULL;
            const f32x2* kp = (const f32x2*)&ks[j][0];
            #pragma unroll
            for (int c = 0; c < 16; c += 2) {
                fma2(accA, qr[c], kp[c]);
                fma2(accB, qr[c + 1], kp[c + 1]);
            }
            float a0, a1, b0, b1;
            unpack2(accA, a0, a1);
            unpack2(accB, b0, b1);
            float s = (a0 + a1) + (b0 + b1);
            ps[iA][j] = __expf(s * scale + ps[iA][j]);
        }
        __syncthreads();
        // phase B: o += P @ V
        #pragma unroll 4
        for (int j = 0; j < 64; j++) {
            float p = ps[iA][j];
            lsum += p;
            f32x2 pd = pack2(p, p);
            const f32x2* vp = (const f32x2*)&vs[j][dg * 8];
            fma2(o2[0], pd, vp[0]);
            fma2(o2[1], pd, vp[1]);
            fma2(o2[2], pd, vp[2]);
            fma2(o2[3], pd, vp[3]);
        }
    }
    float inv = 1.0f / lsum;
    float* op = g_o + (size_t)(i0 + iA) * 256 + h * 32 + dg * 8;
    #pragma unroll
    for (int q = 0; q < 4; q++) {
        float lo, hi;
        unpack2(o2[q], lo, hi);
        op[2 * q] = lo * inv;
        op[2 * q + 1] = hi * inv;
    }
}

// ---------------- final projection: out = c_skip*x + c_out*(h @ outW^T + out_b) ----------------
__global__ void k_final(const float* __restrict__ x, const float* __restrict__ oW,
                        const float* __restrict__ ob, float* __restrict__ out) {
    int row = blockIdx.x;
    int w = threadIdx.x >> 5, lane = threadIdx.x & 31;
    const float* hr = g_h + (size_t)row * 256;
    const float* wr = oW + w * 256;
    float acc = 0.0f;
    #pragma unroll
    for (int c = lane; c < 256; c += 32) acc += hr[c] * wr[c];
    #pragma unroll
    for (int off = 16; off > 0; off >>= 1)
        acc += __shfl_down_sync(0xffffffffu, acc, off);
    if (lane == 0)
        out[row * 3 + w] = g_consts[1] * x[row * 3 + w] + g_consts[2] * (acc + ob[w]);
}

// ---------------- host launcher ----------------
extern "C" void kernel_launch(void* const* d_in, const int* in_sizes, int n_in,
                              void* d_out, int out_size) {
    const float* x_noisy  = (const float*)d_in[0];
    const float* sigma    = (const float*)d_in[1];
    const float* single   = (const float*)d_in[2];
    const float* pair     = (const float*)d_in[3];
    const float* coord_W  = (const float*)d_in[4];
    const float* coord_b  = (const float*)d_in[5];
    const float* single_W = (const float*)d_in[6];
    const float* single_b = (const float*)d_in[7];
    const float* tmlp_W1  = (const float*)d_in[8];
    const float* tmlp_b1  = (const float*)d_in[9];
    const float* tmlp_W2  = (const float*)d_in[10];
    const float* tmlp_b2  = (const float*)d_in[11];
    const float* ada1_g   = (const float*)d_in[12];
    const float* ada1_b   = (const float*)d_in[13];
    const float* ada1_pW  = (const float*)d_in[14];
    const float* ada1_pb  = (const float*)d_in[15];
    const float* qW       = (const float*)d_in[16];
    const float* kW       = (const float*)d_in[17];
    const float* vW       = (const float*)d_in[18];
    const float* pairW    = (const float*)d_in[19];
    const float* outW     = (const float*)d_in[20];
    const float* outb     = (const float*)d_in[21];
    const float* ada2_g   = (const float*)d_in[22];
    const float* ada2_b   = (const float*)d_in[23];
    const float* ada2_pW  = (const float*)d_in[24];
    const float* ada2_pb  = (const float*)d_in[25];
    const float* ffn_W1   = (const float*)d_in[26];
    const float* ffn_b1   = (const float*)d_in[27];
    const float* ffn_W2   = (const float*)d_in[28];
    const float* ffn_b2   = (const float*)d_in[29];
    const float* out_W    = (const float*)d_in[30];
    const float* out_b    = (const float*)d_in[31];
    float* out = (float*)d_out;

    k_consts<<<1, 1>>>(sigma);
    k_temb<<<1, 1024>>>(tmlp_W1, tmlp_b1);
    k_tc<<<1, 256>>>(tmlp_W2, tmlp_b2);
    k_ada<<<16, 256>>>(ada1_pW, ada1_pb, ada2_pW, ada2_pb);
    k_pairbias<<<(int)(L2 / 128), 128>>>(pair, pairW);

    // h init: single @ single_W^T + single_b + (c_in*x) @ coord_W^T + coord_b
    k_gemm<EPI_BIAS | EPI_COORD><<<dim3(4, 32), 256>>>(
        single, -1, single_W, single_b, -1, 0, 256, 256, x_noisy, coord_W, coord_b);

    for (int b = 0; b < NB; b++) {
        k_adaln<<<L, 256>>>(ada1_g + b * 256, ada1_b + b * 256, b, 0);
        k_gemm<0><<<dim3(4, 32), 256>>>(nullptr, 1, qW + (size_t)b * 65536, nullptr, -1, 2, 256, 256, nullptr, nullptr, nullptr);
        k_gemm<0><<<dim3(4, 32), 256>>>(nullptr, 1, kW + (size_t)b * 65536, nullptr, -1, 3, 256, 256, nullptr, nullptr, nullptr);
        k_gemm<0><<<dim3(4, 32), 256>>>(nullptr, 1, vW + (size_t)b * 65536, nullptr, -1, 4, 256, 256, nullptr, nullptr, nullptr);
        k_attn<<<dim3(32, 8), 256>>>(b);
        // h = h + o @ outW^T + outb
        k_gemm<EPI_BIAS | EPI_RES><<<dim3(4, 32), 256>>>(
            nullptr, 5, outW + (size_t)b * 65536, outb + b * 256, 0, 0, 256, 256, nullptr, nullptr, nullptr);
        k_adaln<<<L, 256>>>(ada2_g + b * 256, ada2_b + b * 256, b, 1);
        // ffn1: gelu(h2 @ W1^T + b1)
        k_gemm<EPI_BIAS | EPI_GELU><<<dim3(16, 32), 256>>>(
            nullptr, 1, ffn_W1 + (size_t)b * 262144, ffn_b1 + b * 1024, -1, 6, 256, 1024, nullptr, nullptr, nullptr);
        // ffn2: h = h + t @ W2^T + b2
        k_gemm<EPI_BIAS | EPI_RES><<<dim3(4, 32), 256>>>(
            nullptr, 6, ffn_W2 + (size_t)b * 262144, ffn_b2 + b * 256, 0, 0, 1024, 256, nullptr, nullptr, nullptr);
    }
    k_final<<<L, 96>>>(x_noisy, out_W, out_b, out);
}

// round 7
// speedup vs baseline: 1.0124x; 1.0083x over previous
#include <cuda_runtime.h>
#include <cuda_fp16.h>
#include <math.h>

#define L 2048
#define CA 256
#define NH 8
#define HD 32
#define NB 4
static const size_t L2 = (size_t)L * L;

// ---------------- scratch (device globals; no allocation allowed) ----------------
__device__ float g_consts[4];           // c_in, c_skip, c_out, c_noise
__device__ float g_hidden[1024];
__device__ float g_tc[256];
__device__ float g_ss1[NB][512];
__device__ float g_ss2[NB][512];
__device__ float g_h[L * CA];
__device__ float g_h1[L * CA];
__device__ float g_q[L * CA];
__device__ float g_k[L * CA];
__device__ float g_v[L * CA];
__device__ float g_o[L * CA];
__device__ float g_ffn[L * 1024];
__device__ __half g_bias[134217728];    // [NB*NH][L][L] fp16 = 256 MB

__device__ __forceinline__ float* bufsel(int s) {
    switch (s) {
        case 0: return g_h;
        case 1: return g_h1;
        case 2: return g_q;
        case 3: return g_k;
        case 4: return g_v;
        case 5: return g_o;
        case 6: return g_ffn;
    }
    return nullptr;
}

// ---------------- packed f32x2 helpers (FFMA2: 2x fp32 FMA throughput) ----------------
typedef unsigned long long f32x2;

__device__ __forceinline__ f32x2 pack2(float lo, float hi) {
    f32x2 r;
    asm("mov.b64 %0, {%1, %2};" : "=l"(r) : "f"(lo), "f"(hi));
    return r;
}
__device__ __forceinline__ void unpack2(f32x2 v, float& a, float& b) {
    asm("mov.b64 {%0, %1}, %2;" : "=f"(a), "=f"(b) : "l"(v));
}
__device__ __forceinline__ void fma2(f32x2& d, f32x2 a, f32x2 b) {
    asm("fma.rn.f32x2 %0, %1, %2, %3;" : "=l"(d) : "l"(a), "l"(b), "l"(d));
}

__device__ __forceinline__ float gelu_exact(float x) {
    return 0.5f * x * (1.0f + erff(x * 0.7071067811865475f));
}

// ---------------- tiny setup kernels ----------------
__global__ void k_consts(const float* sigma) {
    float s = sigma[0];
    float sd2 = 256.0f;
    float s2 = s * s + sd2;
    g_consts[0] = rsqrtf(s2);               // c_in
    g_consts[1] = sd2 / s2;                 // c_skip
    g_consts[2] = s * 16.0f * rsqrtf(s2);   // c_out
    g_consts[3] = 0.25f * logf(s + 1e-8f);  // c_noise
}

__global__ void k_temb(const float* __restrict__ W1, const float* __restrict__ b1) {
    __shared__ float temb[256];
    int t = threadIdx.x;
    float cn = g_consts[3];
    if (t < 256) {
        int j = t & 127;
        float f = expf(-logf(10000.0f) * (float)j / 128.0f);
        float a = cn * f;
        temb[t] = (t < 128) ? cosf(a) : sinf(a);
    }
    __syncthreads();
    const float* w = W1 + (size_t)t * 256;
    float acc = 0.0f;
    #pragma unroll 8
    for (int c = 0; c < 256; c++) acc += temb[c] * w[c];
    g_hidden[t] = gelu_exact(acc + b1[t]);
}

__global__ void k_tc(const float* __restrict__ W2, const float* __restrict__ b2) {
    __shared__ float hid[1024];
    int t = threadIdx.x;
    #pragma unroll
    for (int l = 0; l < 4; l++) hid[t + l * 256] = g_hidden[t + l * 256];
    __syncthreads();
    const float* w = W2 + (size_t)t * 1024;
    float acc = 0.0f;
    #pragma unroll 8
    for (int c = 0; c < 1024; c++) acc += hid[c] * w[c];
    g_tc[t] = acc + b2[t];
}

// ada scale/shift: one warp per output row, coalesced weight reads.
// grid 512 x block 256 (8 warps) -> 4096 outputs.
__global__ void k_ada(const float* __restrict__ pW1, const float* __restrict__ pb1,
                      const float* __restrict__ pW2, const float* __restrict__ pb2) {
    int wid = threadIdx.x >> 5, lane = threadIdx.x & 31;
    int gid = blockIdx.x * 8 + wid;   // 0..4095
    int blk = gid >> 10;
    int which = (gid >> 9) & 1;
    int idx = gid & 511;
    const float* W = which ? pW2 : pW1;
    const float* pb = which ? pb2 : pb1;
    const float* w = W + ((size_t)blk * 512 + idx) * 256;
    float acc = 0.0f;
    #pragma unroll
    for (int c = lane; c < 256; c += 32) acc += g_tc[c] * w[c];
    #pragma unroll
    for (int off = 16; off > 0; off >>= 1)
        acc += __shfl_xor_sync(0xffffffffu, acc, off);
    if (lane == 0) {
        float val = acc + pb[blk * 512 + idx];
        if (which) g_ss2[blk][idx] = val; else g_ss1[blk][idx] = val;
    }
}

// ---------------- pair bias (fp16 out): bias[bh][r] = sum_c pair[r][c]*pW[bh][c] ----
// grid = L*L/128, block = 128. B pre-duplicated in smem (no pack movs).
__global__ void k_pairbias(const float* __restrict__ pair, const float* __restrict__ pW) {
    __shared__ __align__(16) float As[64][130];    // As[c][m]
    __shared__ __align__(16) float2 Bsd[64][33];   // Bsd[c][bh] = (b,b)
    size_t r0 = (size_t)blockIdx.x * 128;
    int tid = threadIdx.x;
    const float* Ap = pair + r0 * 64;
    #pragma unroll 8
    for (int l = 0; l < 64; l++) {
        int idx = tid + l * 128;
        As[idx & 63][idx >> 6] = Ap[idx];
    }
    #pragma unroll
    for (int l = 0; l < 16; l++) {
        int idx = tid + l * 128;
        float v = pW[idx];
        Bsd[idx & 63][idx >> 6] = make_float2(v, v);
    }
    __syncthreads();
    int rg = tid & 15;     // rows rg*2 + 32*ii + {0,1}
    int cg = tid >> 4;     // bh = cg*4 + j
    f32x2 acc2[4][4];
    #pragma unroll
    for (int i = 0; i < 4; i++)
        #pragma unroll
        for (int j = 0; j < 4; j++) acc2[i][j] = 0ULL;

    #pragma unroll 4
    for (int c = 0; c < 64; c++) {
        f32x2 a2[4];
        #pragma unroll
        for (int ii = 0; ii < 4; ii++)
            a2[ii] = *(const f32x2*)&As[c][rg * 2 + 32 * ii];
        #pragma unroll
        for (int j = 0; j < 4; j++) {
            f32x2 bd = *(const f32x2*)&Bsd[c][cg * 4 + j];
            #pragma unroll
            for (int ii = 0; ii < 4; ii++) fma2(acc2[ii][j], a2[ii], bd);
        }
    }
    #pragma unroll
    for (int j = 0; j < 4; j++) {
        int bh = cg * 4 + j;
        __half* bp = g_bias + (size_t)bh * L2 + r0 + rg * 2;
        #pragma unroll
        for (int ii = 0; ii < 4; ii++) {
            float lo, hi;
            unpack2(acc2[ii][j], lo, hi);
            *(__half2*)(bp + 32 * ii) = __floats2half2_rn(lo, hi);
        }
    }
}

// ---------------- generic GEMM: C[M,N] = epi(A[M,K] @ W[N,K]^T) ----------------
// BM=BN=64, BK=32, 256 threads. blockIdx.z selects W (qkv fusion) and C buffer.
#define EPI_BIAS  1
#define EPI_GELU  2
#define EPI_RES   4
#define EPI_COORD 8

template <int EPI>
__global__ void k_gemm(const float* __restrict__ Aext, int a_sel,
                       const float* __restrict__ Wa, const float* __restrict__ Wb,
                       const float* __restrict__ Wc,
                       const float* __restrict__ bias,
                       int res_sel, int c_sel0, int K, int N,
                       const float* __restrict__ x3,
                       const float* __restrict__ cw3,
                       const float* __restrict__ cb3) {
    __shared__ __align__(16) float As[32][66];
    __shared__ __align__(16) float2 Bs[32][65];   // duplicated (b,b)
    const float* A = (a_sel >= 0) ? bufsel(a_sel) : Aext;
    int z = blockIdx.z;
    const float* W = (z == 0) ? Wa : (z == 1 ? Wb : Wc);
    float* C = bufsel(c_sel0 + z);
    int m0 = blockIdx.y * 64, n0 = blockIdx.x * 64;
    int tid = threadIdx.x, tx = tid & 15, ty = tid >> 4;

    f32x2 acc2[2][4];
    #pragma unroll
    for (int i = 0; i < 2; i++)
        #pragma unroll
        for (int j = 0; j < 4; j++) acc2[i][j] = 0ULL;

    for (int kt = 0; kt < K; kt += 32) {
        __syncthreads();
        #pragma unroll
        for (int l = 0; l < 8; l++) {
            int idx = tid + l * 256;
            int r = idx >> 5, c = idx & 31;
            As[c][r] = A[(size_t)(m0 + r) * K + kt + c];
            float w = W[(size_t)(n0 + r) * K + kt + c];
            Bs[c][r] = make_float2(w, w);
        }
        __syncthreads();
        #pragma unroll 8
        for (int k = 0; k < 32; k++) {
            f32x2 a2[2];
            a2[0] = *(const f32x2*)&As[k][ty * 4];
            a2[1] = *(const f32x2*)&As[k][ty * 4 + 2];
            f32x2 bd0 = *(const f32x2*)&Bs[k][tx];
            f32x2 bd1 = *(const f32x2*)&Bs[k][tx + 16];
            f32x2 bd2 = *(const f32x2*)&Bs[k][tx + 32];
            f32x2 bd3 = *(const f32x2*)&Bs[k][tx + 48];
            fma2(acc2[0][0], a2[0], bd0); fma2(acc2[1][0], a2[1], bd0);
            fma2(acc2[0][1], a2[0], bd1); fma2(acc2[1][1], a2[1], bd1);
            fma2(acc2[0][2], a2[0], bd2); fma2(acc2[1][2], a2[1], bd2);
            fma2(acc2[0][3], a2[0], bd3); fma2(acc2[1][3], a2[1], bd3);
        }
    }
    const float* res = nullptr;
    if (EPI & EPI_RES) res = bufsel(res_sel);
    float cin = (EPI & EPI_COORD) ? g_consts[0] : 0.0f;
    #pragma unroll
    for (int ip = 0; ip < 2; ip++) {
        #pragma unroll
        for (int j = 0; j < 4; j++) {
            float v0, v1;
            unpack2(acc2[ip][j], v0, v1);
            int col = n0 + tx + 16 * j;
            #pragma unroll
            for (int rr = 0; rr < 2; rr++) {
                int row = m0 + ty * 4 + ip * 2 + rr;
                float v = rr ? v1 : v0;
                if (EPI & EPI_BIAS) v += bias[col];
                if (EPI & EPI_COORD) {
                    v += cin * (x3[row * 3 + 0] * cw3[col * 3 + 0] +
                                x3[row * 3 + 1] * cw3[col * 3 + 1] +
                                x3[row * 3 + 2] * cw3[col * 3 + 2]) + cb3[col];
                }
                if (EPI & EPI_GELU) v = gelu_exact(v);
                if (EPI & EPI_RES) v += res[(size_t)row * N + col];
                C[(size_t)row * N + col] = v;
            }
        }
    }
}

// ---------------- adaLN (h -> h1), one block per row ----------------
__global__ void k_adaln(const float* __restrict__ gamma, const float* __restrict__ beta,
                        int b, int which) {
    __shared__ float red[2][8];
    int row = blockIdx.x, t = threadIdx.x;
    int lane = t & 31, wid = t >> 5;
    float x = g_h[(size_t)row * 256 + t];
    float s1 = x, s2 = x * x;
    #pragma unroll
    for (int off = 16; off > 0; off >>= 1) {
        s1 += __shfl_xor_sync(0xffffffffu, s1, off);
        s2 += __shfl_xor_sync(0xffffffffu, s2, off);
    }
    if (lane == 0) { red[0][wid] = s1; red[1][wid] = s2; }
    __syncthreads();
    float S = 0.0f, Q = 0.0f;
    #pragma unroll
    for (int w = 0; w < 8; w++) { S += red[0][w]; Q += red[1][w]; }
    float mu = S * (1.0f / 256.0f);
    float var = Q * (1.0f / 256.0f) - mu * mu;
    float rs = rsqrtf(var + 1e-5f);
    const float* ss = which ? g_ss2[b] : g_ss1[b];
    float scale = ss[t], shift = ss[256 + t];
    g_h1[(size_t)row * 256 + t] =
        ((x - mu) * rs * gamma[t] + beta[t]) * (1.0f + scale) + shift;
}

// ---------------- attention: grid (L/64, NH), 256 threads ----------------
// Unnormalized softmax (logits provably small). Conflict-free smem mappings:
//   j = (tid&3) + 4*jj  -> K-row LDS64 banks 2j distinct (was 4-way conflict)
//   ps stride 68        -> exp RMW banks 4*iA + j all distinct
__global__ void k_attn(int b) {
    __shared__ __align__(16) float qs[64][34];
    __shared__ __align__(16) float ks[64][34];
    __shared__ __align__(16) float vs[64][32];
    __shared__ __align__(16) float ps[64][68];

    int i0 = blockIdx.x * 64, h = blockIdx.y;
    const __half* bias = g_bias + (size_t)(b * NH + h) * L2;
    int tid = threadIdx.x;

    #pragma unroll
    for (int l = 0; l < 8; l++) {
        int idx = tid + l * 256;
        int r = idx >> 5, c = idx & 31;
        qs[r][c] = g_q[(size_t)(i0 + r) * 256 + h * 32 + c];
    }
    __syncthreads();

    int iA = tid >> 2, jg = tid & 3;
    int dg = tid & 3;
    f32x2 qr[16];
    #pragma unroll
    for (int c = 0; c < 16; c++) qr[c] = *(const f32x2*)&qs[iA][2 * c];

    f32x2 o2[4] = {0ULL, 0ULL, 0ULL, 0ULL};
    float lsum = 0.0f;
    const float scale = 0.1767766952966369f;  // 1/sqrt(32)

    for (int jt = 0; jt < 32; jt++) {
        int j0 = jt * 64;
        __syncthreads();
        #pragma unroll
        for (int l = 0; l < 8; l++) {
            int idx = tid + l * 256;
            int r = idx >> 5, c = idx & 31;
            ks[r][c] = g_k[(size_t)(j0 + r) * 256 + h * 32 + c];
            vs[r][c] = g_v[(size_t)(j0 + r) * 256 + h * 32 + c];
        }
        // stage fp16 bias tile -> ps (float)
        #pragma unroll
        for (int l = 0; l < 8; l++) {
            int idx = tid + l * 256;
            int r = idx >> 5, c2 = idx & 31;
            __half2 hv = *(const __half2*)(bias + (size_t)(i0 + r) * L + j0 + 2 * c2);
            float2 f = __half22float2(hv);
            *(float2*)&ps[r][2 * c2] = f;
        }
        __syncthreads();
        // phase A: S tile + exp, in place over staged bias
        #pragma unroll 2
        for (int jj = 0; jj < 16; jj++) {
            int j = jg + 4 * jj;
            f32x2 accA = 0ULL, accB = 0ULL;
            const f32x2* kp = (const f32x2*)&ks[j][0];
            #pragma unroll
            for (int c = 0; c < 16; c += 2) {
                fma2(accA, qr[c], kp[c]);
                fma2(accB, qr[c + 1], kp[c + 1]);
            }
            float a0, a1, b0, b1;
            unpack2(accA, a0, a1);
            unpack2(accB, b0, b1);
            float s = (a0 + a1) + (b0 + b1);
            ps[iA][j] = __expf(s * scale + ps[iA][j]);
        }
        __syncthreads();
        // phase B: o += P @ V
        #pragma unroll 4
        for (int j = 0; j < 64; j++) {
            float p = ps[iA][j];
            lsum += p;
            f32x2 pd = pack2(p, p);
            const f32x2* vp = (const f32x2*)&vs[j][dg * 8];
            fma2(o2[0], pd, vp[0]);
            fma2(o2[1], pd, vp[1]);
            fma2(o2[2], pd, vp[2]);
            fma2(o2[3], pd, vp[3]);
        }
    }
    float inv = 1.0f / lsum;
    float* op = g_o + (size_t)(i0 + iA) * 256 + h * 32 + dg * 8;
    #pragma unroll
    for (int q = 0; q < 4; q++) {
        float lo, hi;
        unpack2(o2[q], lo, hi);
        op[2 * q] = lo * inv;
        op[2 * q + 1] = hi * inv;
    }
}

// ---------------- final projection ----------------
__global__ void k_final(const float* __restrict__ x, const float* __restrict__ oW,
                        const float* __restrict__ ob, float* __restrict__ out) {
    int row = blockIdx.x;
    int w = threadIdx.x >> 5, lane = threadIdx.x & 31;
    const float* hr = g_h + (size_t)row * 256;
    const float* wr = oW + w * 256;
    float acc = 0.0f;
    #pragma unroll
    for (int c = lane; c < 256; c += 32) acc += hr[c] * wr[c];
    #pragma unroll
    for (int off = 16; off > 0; off >>= 1)
        acc += __shfl_down_sync(0xffffffffu, acc, off);
    if (lane == 0)
        out[row * 3 + w] = g_consts[1] * x[row * 3 + w] + g_consts[2] * (acc + ob[w]);
}

// ---------------- host launcher ----------------
extern "C" void kernel_launch(void* const* d_in, const int* in_sizes, int n_in,
                              void* d_out, int out_size) {
    const float* x_noisy  = (const float*)d_in[0];
    const float* sigma    = (const float*)d_in[1];
    const float* single   = (const float*)d_in[2];
    const float* pair     = (const float*)d_in[3];
    const float* coord_W  = (const float*)d_in[4];
    const float* coord_b  = (const float*)d_in[5];
    const float* single_W = (const float*)d_in[6];
    const float* single_b = (const float*)d_in[7];
    const float* tmlp_W1  = (const float*)d_in[8];
    const float* tmlp_b1  = (const float*)d_in[9];
    const float* tmlp_W2  = (const float*)d_in[10];
    const float* tmlp_b2  = (const float*)d_in[11];
    const float* ada1_g   = (const float*)d_in[12];
    const float* ada1_b   = (const float*)d_in[13];
    const float* ada1_pW  = (const float*)d_in[14];
    const float* ada1_pb  = (const float*)d_in[15];
    const float* qW       = (const float*)d_in[16];
    const float* kW       = (const float*)d_in[17];
    const float* vW       = (const float*)d_in[18];
    const float* pairW    = (const float*)d_in[19];
    const float* outW     = (const float*)d_in[20];
    const float* outb     = (const float*)d_in[21];
    const float* ada2_g   = (const float*)d_in[22];
    const float* ada2_b   = (const float*)d_in[23];
    const float* ada2_pW  = (const float*)d_in[24];
    const float* ada2_pb  = (const float*)d_in[25];
    const float* ffn_W1   = (const float*)d_in[26];
    const float* ffn_b1   = (const float*)d_in[27];
    const float* ffn_W2   = (const float*)d_in[28];
    const float* ffn_b2   = (const float*)d_in[29];
    const float* out_W    = (const float*)d_in[30];
    const float* out_b    = (const float*)d_in[31];
    float* out = (float*)d_out;

    k_consts<<<1, 1>>>(sigma);
    k_temb<<<1, 1024>>>(tmlp_W1, tmlp_b1);
    k_tc<<<1, 256>>>(tmlp_W2, tmlp_b2);
    k_ada<<<512, 256>>>(ada1_pW, ada1_pb, ada2_pW, ada2_pb);
    k_pairbias<<<(int)(L2 / 128), 128>>>(pair, pairW);

    // h init: single @ single_W^T + single_b + (c_in*x) @ coord_W^T + coord_b
    k_gemm<EPI_BIAS | EPI_COORD><<<dim3(4, 32, 1), 256>>>(
        single, -1, single_W, single_W, single_W, single_b, -1, 0, 256, 256,
        x_noisy, coord_W, coord_b);

    for (int b = 0; b < NB; b++) {
        k_adaln<<<L, 256>>>(ada1_g + b * 256, ada1_b + b * 256, b, 0);
        // fused q/k/v via blockIdx.z
        k_gemm<0><<<dim3(4, 32, 3), 256>>>(
            nullptr, 1, qW + (size_t)b * 65536, kW + (size_t)b * 65536,
            vW + (size_t)b * 65536, nullptr, -1, 2, 256, 256,
            nullptr, nullptr, nullptr);
        k_attn<<<dim3(32, 8), 256>>>(b);
        // h = h + o @ outW^T + outb
        k_gemm<EPI_BIAS | EPI_RES><<<dim3(4, 32, 1), 256>>>(
            nullptr, 5, outW + (size_t)b * 65536, outW, outW, outb + b * 256,
            0, 0, 256, 256, nullptr, nullptr, nullptr);
        k_adaln<<<L, 256>>>(ada2_g + b * 256, ada2_b + b * 256, b, 1);
        // ffn1: gelu(h2 @ W1^T + b1)
        k_gemm<EPI_BIAS | EPI_GELU><<<dim3(16, 32, 1), 256>>>(
            nullptr, 1, ffn_W1 + (size_t)b * 262144, ffn_W1, ffn_W1,
            ffn_b1 + b * 1024, -1, 6, 256, 1024, nullptr, nullptr, nullptr);
        // ffn2: h = h + t @ W2^T + b2
        k_gemm<EPI_BIAS | EPI_RES><<<dim3(4, 32, 1), 256>>>(
            nullptr, 6, ffn_W2 + (size_t)b * 262144, ffn_W2, ffn_W2,
            ffn_b2 + b * 256, 0, 0, 1024, 256, nullptr, nullptr, nullptr);
    }
    k_final<<<L, 96>>>(x_noisy, out_W, out_b, out);
}

// round 10
// speedup vs baseline: 1.4529x; 1.4351x over previous
#include <cuda_runtime.h>
#include <cuda_fp16.h>
#include <math.h>

#define L 2048
#define CA 256
#define NH 8
#define HD 32
#define NB 4
static const size_t L2 = (size_t)L * L;

// ---------------- scratch (device globals; no allocation allowed) ----------------
__device__ float g_consts[4];           // c_in, c_skip, c_out, c_noise
__device__ float g_tc[256];
__device__ float g_ss1[NB][512];
__device__ float g_ss2[NB][512];
__device__ float g_h[L * CA];
__device__ float g_h1[L * CA];
__device__ float g_q[L * CA];
__device__ float g_k[L * CA];
__device__ float g_v[L * CA];
__device__ float g_o[L * CA];
__device__ float g_ffn[L * 1024];
__device__ __half g_bias[134217728];    // [NB*NH][L][L] fp16 = 256 MB

__device__ __forceinline__ float* bufsel(int s) {
    switch (s) {
        case 0: return g_h;
        case 1: return g_h1;
        case 2: return g_q;
        case 3: return g_k;
        case 4: return g_v;
        case 5: return g_o;
        case 6: return g_ffn;
    }
    return nullptr;
}

// ---------------- packed f32x2 helpers (FFMA2) ----------------
typedef unsigned long long f32x2;

__device__ __forceinline__ f32x2 pack2(float lo, float hi) {
    f32x2 r;
    asm("mov.b64 %0, {%1, %2};" : "=l"(r) : "f"(lo), "f"(hi));
    return r;
}
__device__ __forceinline__ void unpack2(f32x2 v, float& a, float& b) {
    asm("mov.b64 {%0, %1}, %2;" : "=f"(a), "=f"(b) : "l"(v));
}
__device__ __forceinline__ void fma2(f32x2& d, f32x2 a, f32x2 b) {
    asm("fma.rn.f32x2 %0, %1, %2, %3;" : "=l"(d) : "l"(a), "l"(b), "l"(d));
}

__device__ __forceinline__ float gelu_exact(float x) {
    return 0.5f * x * (1.0f + erff(x * 0.7071067811865475f));
}

// ---------------- merged setup: consts + time MLP (1 CTA, 1024 threads) ----------------
__global__ void k_setup(const float* __restrict__ sigma,
                        const float* __restrict__ W1, const float* __restrict__ b1,
                        const float* __restrict__ W2, const float* __restrict__ b2) {
    __shared__ float temb[256];
    __shared__ float hid[1024];
    int t = threadIdx.x;
    float s = sigma[0];
    if (t == 0) {
        float s2 = s * s + 256.0f;
        g_consts[0] = rsqrtf(s2);               // c_in
        g_consts[1] = 256.0f / s2;              // c_skip
        g_consts[2] = s * 16.0f * rsqrtf(s2);   // c_out
        g_consts[3] = 0.25f * logf(s + 1e-8f);  // c_noise
    }
    float cn = 0.25f * logf(s + 1e-8f);
    if (t < 256) {
        int j = t & 127;
        float f = expf(-logf(10000.0f) * (float)j / 128.0f);
        float a = cn * f;
        temb[t] = (t < 128) ? cosf(a) : sinf(a);
    }
    __syncthreads();
    {
        const float* w = W1 + (size_t)t * 256;
        float acc = 0.0f;
        #pragma unroll 8
        for (int c = 0; c < 256; c++) acc += temb[c] * w[c];
        hid[t] = gelu_exact(acc + b1[t]);
    }
    __syncthreads();
    if (t < 256) {
        const float* w = W2 + (size_t)t * 1024;
        float acc = 0.0f;
        #pragma unroll 8
        for (int c = 0; c < 1024; c++) acc += hid[c] * w[c];
        g_tc[t] = acc + b2[t];
    }
}

// ada scale/shift: one warp per output row, coalesced weight reads.
__global__ void k_ada(const float* __restrict__ pW1, const float* __restrict__ pb1,
                      const float* __restrict__ pW2, const float* __restrict__ pb2) {
    int wid = threadIdx.x >> 5, lane = threadIdx.x & 31;
    int gid = blockIdx.x * 8 + wid;   // 0..4095
    int blk = gid >> 10;
    int which = (gid >> 9) & 1;
    int idx = gid & 511;
    const float* W = which ? pW2 : pW1;
    const float* pb = which ? pb2 : pb1;
    const float* w = W + ((size_t)blk * 512 + idx) * 256;
    float acc = 0.0f;
    #pragma unroll
    for (int c = lane; c < 256; c += 32) acc += g_tc[c] * w[c];
    #pragma unroll
    for (int off = 16; off > 0; off >>= 1)
        acc += __shfl_xor_sync(0xffffffffu, acc, off);
    if (lane == 0) {
        float val = acc + pb[blk * 512 + idx];
        if (which) g_ss2[blk][idx] = val; else g_ss1[blk][idx] = val;
    }
}

// ---------------- pair bias (fp16 out): bias[bh][r] = sum_c pair[r][c]*pW[bh][c] ----
// grid = L*L/128, block = 128. float4 staging, 8-deep load batches for MLP.
__global__ void __launch_bounds__(128) k_pairbias(const float* __restrict__ pair,
                                                  const float* __restrict__ pW) {
    __shared__ __align__(16) float As[64][130];    // As[c][m]
    __shared__ __align__(16) float2 Bsd[64][33];   // Bsd[c][bh] = (b,b)
    size_t r0 = (size_t)blockIdx.x * 128;
    int tid = threadIdx.x;
    const float4* Ap4 = (const float4*)(pair + r0 * 64);
    #pragma unroll
    for (int l = 0; l < 16; l += 8) {
        float4 tmp[8];
        #pragma unroll
        for (int q = 0; q < 8; q++) tmp[q] = Ap4[tid + (l + q) * 128];
        #pragma unroll
        for (int q = 0; q < 8; q++) {
            int idx = tid + (l + q) * 128;   // 0..2047
            int m = idx >> 4, cq = idx & 15;
            As[4 * cq + 0][m] = tmp[q].x;
            As[4 * cq + 1][m] = tmp[q].y;
            As[4 * cq + 2][m] = tmp[q].z;
            As[4 * cq + 3][m] = tmp[q].w;
        }
    }
    #pragma unroll
    for (int l = 0; l < 16; l++) {
        int idx = tid + l * 128;
        float v = pW[idx];
        Bsd[idx & 63][idx >> 6] = make_float2(v, v);
    }
    __syncthreads();
    int rg = tid & 15;     // rows rg*2 + 32*ii + {0,1}
    int cg = tid >> 4;     // bh = cg*4 + j
    f32x2 acc2[4][4];
    #pragma unroll
    for (int i = 0; i < 4; i++)
        #pragma unroll
        for (int j = 0; j < 4; j++) acc2[i][j] = 0ULL;

    #pragma unroll 4
    for (int c = 0; c < 64; c++) {
        f32x2 a2[4];
        #pragma unroll
        for (int ii = 0; ii < 4; ii++)
            a2[ii] = *(const f32x2*)&As[c][rg * 2 + 32 * ii];
        #pragma unroll
        for (int j = 0; j < 4; j++) {
            f32x2 bd = *(const f32x2*)&Bsd[c][cg * 4 + j];
            #pragma unroll
            for (int ii = 0; ii < 4; ii++) fma2(acc2[ii][j], a2[ii], bd);
        }
    }
    #pragma unroll
    for (int j = 0; j < 4; j++) {
        int bh = cg * 4 + j;
        __half* bp = g_bias + (size_t)bh * L2 + r0 + rg * 2;
        #pragma unroll
        for (int ii = 0; ii < 4; ii++) {
            float lo, hi;
            unpack2(acc2[ii][j], lo, hi);
            *(__half2*)(bp + 32 * ii) = __floats2half2_rn(lo, hi);
        }
    }
}

// ---------------- generic GEMM: C[M,N] = epi(A[M,K] @ W[N,K]^T) ----------------
#define EPI_BIAS  1
#define EPI_GELU  2
#define EPI_RES   4
#define EPI_COORD 8

template <int EPI>
__global__ void __launch_bounds__(256) k_gemm(
                       const float* __restrict__ Aext, int a_sel,
                       const float* __restrict__ Wa, const float* __restrict__ Wb,
                       const float* __restrict__ Wc,
                       const float* __restrict__ bias,
                       int res_sel, int c_sel0, int K, int N,
                       const float* __restrict__ x3,
                       const float* __restrict__ cw3,
                       const float* __restrict__ cb3) {
    __shared__ __align__(16) float As[32][66];
    __shared__ __align__(16) float2 Bs[32][65];   // duplicated (b,b)
    const float* A = (a_sel >= 0) ? bufsel(a_sel) : Aext;
    int z = blockIdx.z;
    const float* W = (z == 0) ? Wa : (z == 1 ? Wb : Wc);
    float* C = bufsel(c_sel0 + z);
    int m0 = blockIdx.y * 64, n0 = blockIdx.x * 64;
    int tid = threadIdx.x, tx = tid & 15, ty = tid >> 4;

    f32x2 acc2[2][4];
    #pragma unroll
    for (int i = 0; i < 2; i++)
        #pragma unroll
        for (int j = 0; j < 4; j++) acc2[i][j] = 0ULL;

    for (int kt = 0; kt < K; kt += 32) {
        __syncthreads();
        float av[8], wv[8];
        #pragma unroll
        for (int l = 0; l < 8; l++) {
            int idx = tid + l * 256;
            int r = idx >> 5, c = idx & 31;
            av[l] = A[(size_t)(m0 + r) * K + kt + c];
            wv[l] = W[(size_t)(n0 + r) * K + kt + c];
        }
        #pragma unroll
        for (int l = 0; l < 8; l++) {
            int idx = tid + l * 256;
            int r = idx >> 5, c = idx & 31;
            As[c][r] = av[l];
            Bs[c][r] = make_float2(wv[l], wv[l]);
        }
        __syncthreads();
        #pragma unroll 8
        for (int k = 0; k < 32; k++) {
            f32x2 a2[2];
            a2[0] = *(const f32x2*)&As[k][ty * 4];
            a2[1] = *(const f32x2*)&As[k][ty * 4 + 2];
            f32x2 bd0 = *(const f32x2*)&Bs[k][tx];
            f32x2 bd1 = *(const f32x2*)&Bs[k][tx + 16];
            f32x2 bd2 = *(const f32x2*)&Bs[k][tx + 32];
            f32x2 bd3 = *(const f32x2*)&Bs[k][tx + 48];
            fma2(acc2[0][0], a2[0], bd0); fma2(acc2[1][0], a2[1], bd0);
            fma2(acc2[0][1], a2[0], bd1); fma2(acc2[1][1], a2[1], bd1);
            fma2(acc2[0][2], a2[0], bd2); fma2(acc2[1][2], a2[1], bd2);
            fma2(acc2[0][3], a2[0], bd3); fma2(acc2[1][3], a2[1], bd3);
        }
    }
    const float* res = nullptr;
    if (EPI & EPI_RES) res = bufsel(res_sel);
    float cin = (EPI & EPI_COORD) ? g_consts[0] : 0.0f;
    #pragma unroll
    for (int ip = 0; ip < 2; ip++) {
        #pragma unroll
        for (int j = 0; j < 4; j++) {
            float v0, v1;
            unpack2(acc2[ip][j], v0, v1);
            int col = n0 + tx + 16 * j;
            #pragma unroll
            for (int rr = 0; rr < 2; rr++) {
                int row = m0 + ty * 4 + ip * 2 + rr;
                float v = rr ? v1 : v0;
                if (EPI & EPI_BIAS) v += bias[col];
                if (EPI & EPI_COORD) {
                    v += cin * (x3[row * 3 + 0] * cw3[col * 3 + 0] +
                                x3[row * 3 + 1] * cw3[col * 3 + 1] +
                                x3[row * 3 + 2] * cw3[col * 3 + 2]) + cb3[col];
                }
                if (EPI & EPI_GELU) v = gelu_exact(v);
                if (EPI & EPI_RES) v += res[(size_t)row * N + col];
                C[(size_t)row * N + col] = v;
            }
        }
    }
}

// ---------------- adaLN (h -> h1), one block per row ----------------
__global__ void k_adaln(const float* __restrict__ gamma, const float* __restrict__ beta,
                        int b, int which) {
    __shared__ float red[2][8];
    int row = blockIdx.x, t = threadIdx.x;
    int lane = t & 31, wid = t >> 5;
    float x = g_h[(size_t)row * 256 + t];
    float s1 = x, s2 = x * x;
    #pragma unroll
    for (int off = 16; off > 0; off >>= 1) {
        s1 += __shfl_xor_sync(0xffffffffu, s1, off);
        s2 += __shfl_xor_sync(0xffffffffu, s2, off);
    }
    if (lane == 0) { red[0][wid] = s1; red[1][wid] = s2; }
    __syncthreads();
    float S = 0.0f, Q = 0.0f;
    #pragma unroll
    for (int w = 0; w < 8; w++) { S += red[0][w]; Q += red[1][w]; }
    float mu = S * (1.0f / 256.0f);
    float var = Q * (1.0f / 256.0f) - mu * mu;
    float rs = rsqrtf(var + 1e-5f);
    const float* ss = which ? g_ss2[b] : g_ss1[b];
    float scale = ss[t], shift = ss[256 + t];
    g_h1[(size_t)row * 256 + t] =
        ((x - mu) * rs * gamma[t] + beta[t]) * (1.0f + scale) + shift;
}

// ---------------- attention: grid (L/128, NH) = 128 CTAs (single wave), 512 thr ----
__global__ void __launch_bounds__(512, 1) k_attn(int b) {
    __shared__ __align__(16) float qs[128][34];
    __shared__ __align__(16) float ks[64][34];
    __shared__ __align__(16) float vs[64][32];
    __shared__ __align__(16) float ps[128][68];

    int i0 = blockIdx.x * 128, h = blockIdx.y;
    const __half* bias = g_bias + (size_t)(b * NH + h) * L2;
    int tid = threadIdx.x;

    #pragma unroll
    for (int l = 0; l < 8; l++) {
        int idx = tid + l * 512;
        int r = idx >> 5, c = idx & 31;
        qs[r][c] = g_q[(size_t)(i0 + r) * 256 + h * 32 + c];
    }
    __syncthreads();

    int iA = tid >> 2, jg = tid & 3;
    int dg = tid & 3;
    f32x2 qr[16];
    #pragma unroll
    for (int c = 0; c < 16; c++) qr[c] = *(const f32x2*)&qs[iA][2 * c];

    f32x2 o2[4] = {0ULL, 0ULL, 0ULL, 0ULL};
    float lsum = 0.0f;
    const float scale = 0.1767766952966369f;  // 1/sqrt(32)

    for (int jt = 0; jt < 32; jt++) {
        int j0 = jt * 64;
        __syncthreads();
        #pragma unroll
        for (int l = 0; l < 4; l++) {
            int idx = tid + l * 512;
            int r = idx >> 5, c = idx & 31;
            ks[r][c] = g_k[(size_t)(j0 + r) * 256 + h * 32 + c];
            vs[r][c] = g_v[(size_t)(j0 + r) * 256 + h * 32 + c];
        }
        // stage fp16 bias tile 128x64 -> ps (float)
        #pragma unroll
        for (int l = 0; l < 8; l++) {
            int idx = tid + l * 512;
            int r = idx >> 5, c2 = idx & 31;
            __half2 hv = *(const __half2*)(bias + (size_t)(i0 + r) * L + j0 + 2 * c2);
            float2 f = __half22float2(hv);
            *(float2*)&ps[r][2 * c2] = f;
        }
        __syncthreads();
        // phase A: S tile + exp, in place over staged bias
        #pragma unroll 2
        for (int jj = 0; jj < 16; jj++) {
            int j = jg + 4 * jj;
            f32x2 accA = 0ULL, accB = 0ULL;
            const f32x2* kp = (const f32x2*)&ks[j][0];
            #pragma unroll
            for (int c = 0; c < 16; c += 2) {
                fma2(accA, qr[c], kp[c]);
                fma2(accB, qr[c + 1], kp[c + 1]);
            }
            float a0, a1, b0, b1;
            unpack2(accA, a0, a1);
            unpack2(accB, b0, b1);
            float s = (a0 + a1) + (b0 + b1);
            ps[iA][j] = __expf(s * scale + ps[iA][j]);
        }
        __syncthreads();
        // phase B: o += P @ V
        #pragma unroll 4
        for (int j = 0; j < 64; j++) {
            float p = ps[iA][j];
            lsum += p;
            f32x2 pd = pack2(p, p);
            const f32x2* vp = (const f32x2*)&vs[j][dg * 8];
            fma2(o2[0], pd, vp[0]);
            fma2(o2[1], pd, vp[1]);
            fma2(o2[2], pd, vp[2]);
            fma2(o2[3], pd, vp[3]);
        }
    }
    float inv = 1.0f / lsum;
    float* op = g_o + (size_t)(i0 + iA) * 256 + h * 32 + dg * 8;
    #pragma unroll
    for (int q = 0; q < 4; q++) {
        float lo, hi;
        unpack2(o2[q], lo, hi);
        op[2 * q] = lo * inv;
        op[2 * q + 1] = hi * inv;
    }
}

// ---------------- final projection ----------------
__global__ void k_final(const float* __restrict__ x, const float* __restrict__ oW,
                        const float* __restrict__ ob, float* __restrict__ out) {
    int row = blockIdx.x;
    int w = threadIdx.x >> 5, lane = threadIdx.x & 31;
    const float* hr = g_h + (size_t)row * 256;
    const float* wr = oW + w * 256;
    float acc = 0.0f;
    #pragma unroll
    for (int c = lane; c < 256; c += 32) acc += hr[c] * wr[c];
    #pragma unroll
    for (int off = 16; off > 0; off >>= 1)
        acc += __shfl_down_sync(0xffffffffu, acc, off);
    if (lane == 0)
        out[row * 3 + w] = g_consts[1] * x[row * 3 + w] + g_consts[2] * (acc + ob[w]);
}

// ---------------- host launcher ----------------
extern "C" void kernel_launch(void* const* d_in, const int* in_sizes, int n_in,
                              void* d_out, int out_size) {
    const float* x_noisy  = (const float*)d_in[0];
    const float* sigma    = (const float*)d_in[1];
    const float* single   = (const float*)d_in[2];
    const float* pair     = (const float*)d_in[3];
    const float* coord_W  = (const float*)d_in[4];
    const float* coord_b  = (const float*)d_in[5];
    const float* single_W = (const float*)d_in[6];
    const float* single_b = (const float*)d_in[7];
    const float* tmlp_W1  = (const float*)d_in[8];
    const float* tmlp_b1  = (const float*)d_in[9];
    const float* tmlp_W2  = (const float*)d_in[10];
    const float* tmlp_b2  = (const float*)d_in[11];
    const float* ada1_g   = (const float*)d_in[12];
    const float* ada1_b   = (const float*)d_in[13];
    const float* ada1_pW  = (const float*)d_in[14];
    const float* ada1_pb  = (const float*)d_in[15];
    const float* qW       = (const float*)d_in[16];
    const float* kW       = (const float*)d_in[17];
    const float* vW       = (const float*)d_in[18];
    const float* pairW    = (const float*)d_in[19];
    const float* outW     = (const float*)d_in[20];
    const float* outb     = (const float*)d_in[21];
    const float* ada2_g   = (const float*)d_in[22];
    const float* ada2_b   = (const float*)d_in[23];
    const float* ada2_pW  = (const float*)d_in[24];
    const float* ada2_pb  = (const float*)d_in[25];
    const float* ffn_W1   = (const float*)d_in[26];
    const float* ffn_b1   = (const float*)d_in[27];
    const float* ffn_W2   = (const float*)d_in[28];
    const float* ffn_b2   = (const float*)d_in[29];
    const float* out_W    = (const float*)d_in[30];
    const float* out_b    = (const float*)d_in[31];
    float* out = (float*)d_out;

    // launch order chosen so index 3 (ncu capture slot) = k_pairbias
    k_setup<<<1, 1024>>>(sigma, tmlp_W1, tmlp_b1, tmlp_W2, tmlp_b2);   // 0
    k_ada<<<512, 256>>>(ada1_pW, ada1_pb, ada2_pW, ada2_pb);           // 1
    k_gemm<EPI_BIAS | EPI_COORD><<<dim3(4, 32, 1), 256>>>(             // 2
        single, -1, single_W, single_W, single_W, single_b, -1, 0, 256, 256,
        x_noisy, coord_W, coord_b);
    k_pairbias<<<(int)(L2 / 128), 128>>>(pair, pairW);                 // 3 <- profiled

    for (int b = 0; b < NB; b++) {
        k_adaln<<<L, 256>>>(ada1_g + b * 256, ada1_b + b * 256, b, 0);
        k_gemm<0><<<dim3(4, 32, 3), 256>>>(
            nullptr, 1, qW + (size_t)b * 65536, kW + (size_t)b * 65536,
            vW + (size_t)b * 65536, nullptr, -1, 2, 256, 256,
            nullptr, nullptr, nullptr);
        k_attn<<<dim3(16, 8), 512>>>(b);
        k_gemm<EPI_BIAS | EPI_RES><<<dim3(4, 32, 1), 256>>>(
            nullptr, 5, outW + (size_t)b * 65536, outW, outW, outb + b * 256,
            0, 0, 256, 256, nullptr, nullptr, nullptr);
        k_adaln<<<L, 256>>>(ada2_g + b * 256, ada2_b + b * 256, b, 1);
        k_gemm<EPI_BIAS | EPI_GELU><<<dim3(16, 32, 1), 256>>>(
            nullptr, 1, ffn_W1 + (size_t)b * 262144, ffn_W1, ffn_W1,
            ffn_b1 + b * 1024, -1, 6, 256, 1024, nullptr, nullptr, nullptr);
        k_gemm<EPI_BIAS | EPI_RES><<<dim3(4, 32, 1), 256>>>(
            nullptr, 6, ffn_W2 + (size_t)b * 262144, ffn_W2, ffn_W2,
            ffn_b2 + b * 256, 0, 0, 1024, 256, nullptr, nullptr, nullptr);
    }
    k_final<<<L, 96>>>(x_noisy, out_W, out_b, out);
}

// round 11
// speedup vs baseline: 1.5744x; 1.0836x over previous
#include <cuda_runtime.h>
#include <cuda_fp16.h>
#include <math.h>

#define L 2048
#define CA 256
#define NH 8
#define HD 32
#define NB 4
static const size_t L2 = (size_t)L * L;

// ---------------- scratch (device globals; no allocation allowed) ----------------
__device__ float g_consts[4];           // c_in, c_skip, c_out, c_noise
__device__ float g_tc[256];
__device__ float g_ss1[NB][512];
__device__ float g_ss2[NB][512];
__device__ float g_h[L * CA];
__device__ float g_h1[L * CA];
__device__ float g_q[L * CA];
__device__ float g_k[L * CA];
__device__ float g_v[L * CA];
__device__ float g_o[L * CA];
__device__ float g_ffn[L * 1024];
__device__ __half g_bias[134217728];    // [NB*NH][L][L] fp16 = 256 MB

__device__ __forceinline__ float* bufsel(int s) {
    switch (s) {
        case 0: return g_h;
        case 1: return g_h1;
        case 2: return g_q;
        case 3: return g_k;
        case 4: return g_v;
        case 5: return g_o;
        case 6: return g_ffn;
    }
    return nullptr;
}

// ---------------- packed f32x2 helpers (FFMA2) ----------------
typedef unsigned long long f32x2;

__device__ __forceinline__ f32x2 pack2(float lo, float hi) {
    f32x2 r;
    asm("mov.b64 %0, {%1, %2};" : "=l"(r) : "f"(lo), "f"(hi));
    return r;
}
__device__ __forceinline__ void unpack2(f32x2 v, float& a, float& b) {
    asm("mov.b64 {%0, %1}, %2;" : "=f"(a), "=f"(b) : "l"(v));
}
__device__ __forceinline__ void fma2(f32x2& d, f32x2 a, f32x2 b) {
    asm("fma.rn.f32x2 %0, %1, %2, %3;" : "=l"(d) : "l"(a), "l"(b), "l"(d));
}
__device__ __forceinline__ void add2(f32x2& d, f32x2 a) {
    asm("add.rn.f32x2 %0, %1, %2;" : "=l"(d) : "l"(a), "l"(d));
}

__device__ __forceinline__ float gelu_exact(float x) {
    return 0.5f * x * (1.0f + erff(x * 0.7071067811865475f));
}

// ---------------- merged setup: consts + time MLP (1 CTA, 1024 threads) ----------------
__global__ void k_setup(const float* __restrict__ sigma,
                        const float* __restrict__ W1, const float* __restrict__ b1,
                        const float* __restrict__ W2, const float* __restrict__ b2) {
    __shared__ float temb[256];
    __shared__ float hid[1024];
    int t = threadIdx.x;
    float s = sigma[0];
    if (t == 0) {
        float s2 = s * s + 256.0f;
        g_consts[0] = rsqrtf(s2);               // c_in
        g_consts[1] = 256.0f / s2;              // c_skip
        g_consts[2] = s * 16.0f * rsqrtf(s2);   // c_out
        g_consts[3] = 0.25f * logf(s + 1e-8f);  // c_noise
    }
    float cn = 0.25f * logf(s + 1e-8f);
    if (t < 256) {
        int j = t & 127;
        float f = expf(-logf(10000.0f) * (float)j / 128.0f);
        float a = cn * f;
        temb[t] = (t < 128) ? cosf(a) : sinf(a);
    }
    __syncthreads();
    {
        const float* w = W1 + (size_t)t * 256;
        float acc = 0.0f;
        #pragma unroll 8
        for (int c = 0; c < 256; c++) acc += temb[c] * w[c];
        hid[t] = gelu_exact(acc + b1[t]);
    }
    __syncthreads();
    if (t < 256) {
        const float* w = W2 + (size_t)t * 1024;
        float acc = 0.0f;
        #pragma unroll 8
        for (int c = 0; c < 1024; c++) acc += hid[c] * w[c];
        g_tc[t] = acc + b2[t];
    }
}

// ada scale/shift: one warp per output row, coalesced weight reads.
__global__ void k_ada(const float* __restrict__ pW1, const float* __restrict__ pb1,
                      const float* __restrict__ pW2, const float* __restrict__ pb2) {
    int wid = threadIdx.x >> 5, lane = threadIdx.x & 31;
    int gid = blockIdx.x * 8 + wid;   // 0..4095
    int blk = gid >> 10;
    int which = (gid >> 9) & 1;
    int idx = gid & 511;
    const float* W = which ? pW2 : pW1;
    const float* pb = which ? pb2 : pb1;
    const float* w = W + ((size_t)blk * 512 + idx) * 256;
    float acc = 0.0f;
    #pragma unroll
    for (int c = lane; c < 256; c += 32) acc += g_tc[c] * w[c];
    #pragma unroll
    for (int off = 16; off > 0; off >>= 1)
        acc += __shfl_xor_sync(0xffffffffu, acc, off);
    if (lane == 0) {
        float val = acc + pb[blk * 512 + idx];
        if (which) g_ss2[blk][idx] = val; else g_ss1[blk][idx] = val;
    }
}

// ---------------- pair bias (fp16 out): bias[bh][r] = sum_c pair[r][c]*pW[bh][c] ----
// grid = L*L/128, block = 128. Scalar staging (2-way STS only), low regs.
__global__ void __launch_bounds__(128) k_pairbias(const float* __restrict__ pair,
                                                  const float* __restrict__ pW) {
    __shared__ __align__(16) float As[64][130];    // As[c][m]
    __shared__ __align__(16) float2 Bsd[64][33];   // Bsd[c][bh] = (b,b)
    size_t r0 = (size_t)blockIdx.x * 128;
    int tid = threadIdx.x;
    const float* Ap = pair + r0 * 64;
    #pragma unroll 8
    for (int l = 0; l < 64; l++) {
        int idx = tid + l * 128;
        As[idx & 63][idx >> 6] = Ap[idx];
    }
    #pragma unroll
    for (int l = 0; l < 16; l++) {
        int idx = tid + l * 128;
        float v = pW[idx];
        Bsd[idx & 63][idx >> 6] = make_float2(v, v);
    }
    __syncthreads();
    int rg = tid & 15;     // rows rg*2 + 32*ii + {0,1}
    int cg = tid >> 4;     // bh = cg*4 + j
    f32x2 acc2[4][4];
    #pragma unroll
    for (int i = 0; i < 4; i++)
        #pragma unroll
        for (int j = 0; j < 4; j++) acc2[i][j] = 0ULL;

    #pragma unroll 4
    for (int c = 0; c < 64; c++) {
        f32x2 a2[4];
        #pragma unroll
        for (int ii = 0; ii < 4; ii++)
            a2[ii] = *(const f32x2*)&As[c][rg * 2 + 32 * ii];
        #pragma unroll
        for (int j = 0; j < 4; j++) {
            f32x2 bd = *(const f32x2*)&Bsd[c][cg * 4 + j];
            #pragma unroll
            for (int ii = 0; ii < 4; ii++) fma2(acc2[ii][j], a2[ii], bd);
        }
    }
    #pragma unroll
    for (int j = 0; j < 4; j++) {
        int bh = cg * 4 + j;
        __half* bp = g_bias + (size_t)bh * L2 + r0 + rg * 2;
        #pragma unroll
        for (int ii = 0; ii < 4; ii++) {
            float lo, hi;
            unpack2(acc2[ii][j], lo, hi);
            *(__half2*)(bp + 32 * ii) = __floats2half2_rn(lo, hi);
        }
    }
}

// ---------------- generic GEMM: C[M,N] = epi(A[M,K] @ W[N,K]^T) ----------------
// Tile: BM = 32*RP rows x 64 cols, BK=32, 256 threads.
// Thread: RP m-pairs (f32x2) x 4 n-cols.
#define EPI_BIAS  1
#define EPI_GELU  2
#define EPI_RES   4
#define EPI_COORD 8

template <int RP, int EPI>
__global__ void __launch_bounds__(256) k_gemm(
                       const float* __restrict__ Aext, int a_sel,
                       const float* __restrict__ Wa, const float* __restrict__ Wb,
                       const float* __restrict__ Wc,
                       const float* __restrict__ bias,
                       int res_sel, int c_sel0, int K, int N,
                       const float* __restrict__ x3,
                       const float* __restrict__ cw3,
                       const float* __restrict__ cb3) {
    const int BM = 32 * RP;
    __shared__ __align__(16) float As[32][BM + 2];
    __shared__ __align__(16) float2 Bs[32][65];   // duplicated (b,b)
    const float* A = (a_sel >= 0) ? bufsel(a_sel) : Aext;
    int z = blockIdx.z;
    const float* W = (z == 0) ? Wa : (z == 1 ? Wb : Wc);
    float* C = bufsel(c_sel0 + z);
    int m0 = blockIdx.y * BM, n0 = blockIdx.x * 64;
    int tid = threadIdx.x, tx = tid & 15, ty = tid >> 4;

    f32x2 acc2[RP][4];
    #pragma unroll
    for (int i = 0; i < RP; i++)
        #pragma unroll
        for (int j = 0; j < 4; j++) acc2[i][j] = 0ULL;

    for (int kt = 0; kt < K; kt += 32) {
        __syncthreads();
        #pragma unroll
        for (int l = 0; l < 4 * RP; l++) {
            int idx = tid + l * 256;
            int r = idx >> 5, c = idx & 31;
            As[c][r] = A[(size_t)(m0 + r) * K + kt + c];
        }
        #pragma unroll
        for (int l = 0; l < 8; l++) {
            int idx = tid + l * 256;
            int r = idx >> 5, c = idx & 31;
            float w = W[(size_t)(n0 + r) * K + kt + c];
            Bs[c][r] = make_float2(w, w);
        }
        __syncthreads();
        #pragma unroll 8
        for (int k = 0; k < 32; k++) {
            f32x2 a2[RP];
            #pragma unroll
            for (int ip = 0; ip < RP; ip++)
                a2[ip] = *(const f32x2*)&As[k][ty * 2 * RP + 2 * ip];
            f32x2 bd[4];
            #pragma unroll
            for (int j = 0; j < 4; j++)
                bd[j] = *(const f32x2*)&Bs[k][tx + 16 * j];
            #pragma unroll
            for (int j = 0; j < 4; j++)
                #pragma unroll
                for (int ip = 0; ip < RP; ip++)
                    fma2(acc2[ip][j], a2[ip], bd[j]);
        }
    }
    const float* res = nullptr;
    if (EPI & EPI_RES) res = bufsel(res_sel);
    float cin = (EPI & EPI_COORD) ? g_consts[0] : 0.0f;
    #pragma unroll
    for (int ip = 0; ip < RP; ip++) {
        #pragma unroll
        for (int j = 0; j < 4; j++) {
            float v0, v1;
            unpack2(acc2[ip][j], v0, v1);
            int col = n0 + tx + 16 * j;
            #pragma unroll
            for (int rr = 0; rr < 2; rr++) {
                int row = m0 + ty * 2 * RP + ip * 2 + rr;
                float v = rr ? v1 : v0;
                if (EPI & EPI_BIAS) v += bias[col];
                if (EPI & EPI_COORD) {
                    v += cin * (x3[row * 3 + 0] * cw3[col * 3 + 0] +
                                x3[row * 3 + 1] * cw3[col * 3 + 1] +
                                x3[row * 3 + 2] * cw3[col * 3 + 2]) + cb3[col];
                }
                if (EPI & EPI_GELU) v = gelu_exact(v);
                if (EPI & EPI_RES) v += res[(size_t)row * N + col];
                C[(size_t)row * N + col] = v;
            }
        }
    }
}

// ---------------- adaLN (h -> h1), one block per row ----------------
__global__ void k_adaln(const float* __restrict__ gamma, const float* __restrict__ beta,
                        int b, int which) {
    __shared__ float red[2][8];
    int row = blockIdx.x, t = threadIdx.x;
    int lane = t & 31, wid = t >> 5;
    float x = g_h[(size_t)row * 256 + t];
    float s1 = x, s2 = x * x;
    #pragma unroll
    for (int off = 16; off > 0; off >>= 1) {
        s1 += __shfl_xor_sync(0xffffffffu, s1, off);
        s2 += __shfl_xor_sync(0xffffffffu, s2, off);
    }
    if (lane == 0) { red[0][wid] = s1; red[1][wid] = s2; }
    __syncthreads();
    float S = 0.0f, Q = 0.0f;
    #pragma unroll
    for (int w = 0; w < 8; w++) { S += red[0][w]; Q += red[1][w]; }
    float mu = S * (1.0f / 256.0f);
    float var = Q * (1.0f / 256.0f) - mu * mu;
    float rs = rsqrtf(var + 1e-5f);
    const float* ss = which ? g_ss2[b] : g_ss1[b];
    float scale = ss[t], shift = ss[256 + t];
    g_h1[(size_t)row * 256 + t] =
        ((x - mu) * rs * gamma[t] + beta[t]) * (1.0f + scale) + shift;
}

// ---------------- attention: grid (L/64, NH) = 256 CTAs, 256 threads ----------------
// Register-resident P: each thread owns row iA, j-subset jg+4*jj, full d=32 output.
// Quad shuffle-reduce at the end. Unnormalized softmax (logits provably small).
__global__ void __launch_bounds__(256) k_attn(int b) {
    __shared__ __align__(16) float qs[64][34];
    __shared__ __align__(16) float ks[64][34];
    __shared__ __align__(16) float vs[64][34];
    __shared__ __align__(16) float bs[64][66];

    int i0 = blockIdx.x * 64, h = blockIdx.y;
    const __half* bias = g_bias + (size_t)(b * NH + h) * L2;
    int tid = threadIdx.x;

    #pragma unroll
    for (int l = 0; l < 8; l++) {
        int idx = tid + l * 256;
        int r = idx >> 5, c = idx & 31;
        qs[r][c] = g_q[(size_t)(i0 + r) * 256 + h * 32 + c];
    }
    __syncthreads();

    int iA = tid >> 2, jg = tid & 3;
    f32x2 qr[16];
    #pragma unroll
    for (int c = 0; c < 16; c++) qr[c] = *(const f32x2*)&qs[iA][2 * c];

    f32x2 o2[16];
    #pragma unroll
    for (int c = 0; c < 16; c++) o2[c] = 0ULL;
    float lsum = 0.0f;
    const float scale = 0.1767766952966369f;  // 1/sqrt(32)

    for (int jt = 0; jt < 32; jt++) {
        int j0 = jt * 64;
        __syncthreads();
        #pragma unroll
        for (int l = 0; l < 8; l++) {
            int idx = tid + l * 256;
            int r = idx >> 5, c = idx & 31;
            ks[r][c] = g_k[(size_t)(j0 + r) * 256 + h * 32 + c];
            vs[r][c] = g_v[(size_t)(j0 + r) * 256 + h * 32 + c];
        }
        // stage fp16 bias tile 64x64 -> bs (float)
        #pragma unroll
        for (int l = 0; l < 8; l++) {
            int idx = tid + l * 256;
            int r = idx >> 5, c2 = idx & 31;
            __half2 hv = *(const __half2*)(bias + (size_t)(i0 + r) * L + j0 + 2 * c2);
            *(float2*)&bs[r][2 * c2] = __half22float2(hv);
        }
        __syncthreads();

        // phase A: s = q . k, p = exp(s*scale + bias) kept in registers
        float p[16];
        #pragma unroll 2
        for (int jj = 0; jj < 16; jj++) {
            int j = jg + 4 * jj;
            f32x2 accA = 0ULL, accB = 0ULL;
            const f32x2* kp = (const f32x2*)&ks[j][0];
            #pragma unroll
            for (int c = 0; c < 16; c += 2) {
                fma2(accA, qr[c], kp[c]);
                fma2(accB, qr[c + 1], kp[c + 1]);
            }
            float a0, a1, b0, b1;
            unpack2(accA, a0, a1);
            unpack2(accB, b0, b1);
            float s = (a0 + a1) + (b0 + b1);
            float pv = __expf(s * scale + bs[iA][j]);
            p[jj] = pv;
            lsum += pv;
        }
        // phase B: o += p_j * v_j over full d (p from registers)
        #pragma unroll 2
        for (int jj = 0; jj < 16; jj++) {
            int j = jg + 4 * jj;
            f32x2 pd = pack2(p[jj], p[jj]);
            const f32x2* vp = (const f32x2*)&vs[j][0];
            #pragma unroll
            for (int c = 0; c < 16; c++) fma2(o2[c], pd, vp[c]);
        }
    }
    // quad reduce (lanes jg=0..3 share row iA)
    #pragma unroll
    for (int c = 0; c < 16; c++) {
        add2(o2[c], __shfl_xor_sync(0xffffffffu, o2[c], 1));
        add2(o2[c], __shfl_xor_sync(0xffffffffu, o2[c], 2));
    }
    lsum += __shfl_xor_sync(0xffffffffu, lsum, 1);
    lsum += __shfl_xor_sync(0xffffffffu, lsum, 2);
    float inv = 1.0f / lsum;
    // each quad lane writes its quarter of d
    float* op = g_o + (size_t)(i0 + iA) * 256 + h * 32 + jg * 8;
    #pragma unroll
    for (int q = 0; q < 4; q++) {
        float lo, hi;
        unpack2(o2[jg * 4 + q], lo, hi);
        *(float2*)(op + 2 * q) = make_float2(lo * inv, hi * inv);
    }
}

// ---------------- final projection ----------------
__global__ void k_final(const float* __restrict__ x, const float* __restrict__ oW,
                        const float* __restrict__ ob, float* __restrict__ out) {
    int row = blockIdx.x;
    int w = threadIdx.x >> 5, lane = threadIdx.x & 31;
    const float* hr = g_h + (size_t)row * 256;
    const float* wr = oW + w * 256;
    float acc = 0.0f;
    #pragma unroll
    for (int c = lane; c < 256; c += 32) acc += hr[c] * wr[c];
    #pragma unroll
    for (int off = 16; off > 0; off >>= 1)
        acc += __shfl_down_sync(0xffffffffu, acc, off);
    if (lane == 0)
        out[row * 3 + w] = g_consts[1] * x[row * 3 + w] + g_consts[2] * (acc + ob[w]);
}

// ---------------- host launcher ----------------
extern "C" void kernel_launch(void* const* d_in, const int* in_sizes, int n_in,
                              void* d_out, int out_size) {
    const float* x_noisy  = (const float*)d_in[0];
    const float* sigma    = (const float*)d_in[1];
    const float* single   = (const float*)d_in[2];
    const float* pair     = (const float*)d_in[3];
    const float* coord_W  = (const float*)d_in[4];
    const float* coord_b  = (const float*)d_in[5];
    const float* single_W = (const float*)d_in[6];
    const float* single_b = (const float*)d_in[7];
    const float* tmlp_W1  = (const float*)d_in[8];
    const float* tmlp_b1  = (const float*)d_in[9];
    const float* tmlp_W2  = (const float*)d_in[10];
    const float* tmlp_b2  = (const float*)d_in[11];
    const float* ada1_g   = (const float*)d_in[12];
    const float* ada1_b   = (const float*)d_in[13];
    const float* ada1_pW  = (const float*)d_in[14];
    const float* ada1_pb  = (const float*)d_in[15];
    const float* qW       = (const float*)d_in[16];
    const float* kW       = (const float*)d_in[17];
    const float* vW       = (const float*)d_in[18];
    const float* pairW    = (const float*)d_in[19];
    const float* outW     = (const float*)d_in[20];
    const float* outb     = (const float*)d_in[21];
    const float* ada2_g   = (const float*)d_in[22];
    const float* ada2_b   = (const float*)d_in[23];
    const float* ada2_pW  = (const float*)d_in[24];
    const float* ada2_pb  = (const float*)d_in[25];
    const float* ffn_W1   = (const float*)d_in[26];
    const float* ffn_b1   = (const float*)d_in[27];
    const float* ffn_W2   = (const float*)d_in[28];
    const float* ffn_b2   = (const float*)d_in[29];
    const float* out_W    = (const float*)d_in[30];
    const float* out_b    = (const float*)d_in[31];
    float* out = (float*)d_out;

    k_setup<<<1, 1024>>>(sigma, tmlp_W1, tmlp_b1, tmlp_W2, tmlp_b2);   // 0
    k_ada<<<512, 256>>>(ada1_pW, ada1_pb, ada2_pW, ada2_pb);           // 1
    k_pairbias<<<(int)(L2 / 128), 128>>>(pair, pairW);                 // 2
    // 3 <- profiled: new GEMM template (RP=2, 128 CTAs)
    k_gemm<2, EPI_BIAS | EPI_COORD><<<dim3(4, 32, 1), 256>>>(
        single, -1, single_W, single_W, single_W, single_b, -1, 0, 256, 256,
        x_noisy, coord_W, coord_b);

    for (int b = 0; b < NB; b++) {
        k_adaln<<<L, 256>>>(ada1_g + b * 256, ada1_b + b * 256, b, 0);
        // fused q/k/v, TM=128 tiles: (4,16,3) = 192 CTAs
        k_gemm<4, 0><<<dim3(4, 16, 3), 256>>>(
            nullptr, 1, qW + (size_t)b * 65536, kW + (size_t)b * 65536,
            vW + (size_t)b * 65536, nullptr, -1, 2, 256, 256,
            nullptr, nullptr, nullptr);
        k_attn<<<dim3(32, 8), 256>>>(b);
        // h = h + o @ outW^T + outb  (TM=64: 128 CTAs)
        k_gemm<2, EPI_BIAS | EPI_RES><<<dim3(4, 32, 1), 256>>>(
            nullptr, 5, outW + (size_t)b * 65536, outW, outW, outb + b * 256,
            0, 0, 256, 256, nullptr, nullptr, nullptr);
        k_adaln<<<L, 256>>>(ada2_g + b * 256, ada2_b + b * 256, b, 1);
        // ffn1: gelu(h2 @ W1^T + b1)  (TM=128: (16,16) = 256 CTAs)
        k_gemm<4, EPI_BIAS | EPI_GELU><<<dim3(16, 16, 1), 256>>>(
            nullptr, 1, ffn_W1 + (size_t)b * 262144, ffn_W1, ffn_W1,
            ffn_b1 + b * 1024, -1, 6, 256, 1024, nullptr, nullptr, nullptr);
        // ffn2: h = h + t @ W2^T + b2  (TM=64: 128 CTAs, K=1024)
        k_gemm<2, EPI_BIAS | EPI_RES><<<dim3(4, 32, 1), 256>>>(
            nullptr, 6, ffn_W2 + (size_t)b * 262144, ffn_W2, ffn_W2,
            ffn_b2 + b * 256, 0, 0, 1024, 256, nullptr, nullptr, nullptr);
    }
    k_final<<<L, 96>>>(x_noisy, out_W, out_b, out);
}

// round 14
// speedup vs baseline: 1.7892x; 1.1364x over previous
#include <cuda_runtime.h>
#include <cuda_fp16.h>
#include <math.h>

#define L 2048
#define CA 256
#define NH 8
#define HD 32
#define NB 4
static const size_t L2 = (size_t)L * L;

// ---------------- scratch (device globals; no allocation allowed) ----------------
__device__ float g_consts[4];           // c_in, c_skip, c_out, c_noise
__device__ float g_tc[256];
__device__ float g_ss1[NB][512];
__device__ float g_ss2[NB][512];
__device__ float g_h[L * CA];
__device__ float g_h1[L * CA];
__device__ float g_q[L * CA];
__device__ float g_k[L * CA];
__device__ float g_v[L * CA];
__device__ float g_o[L * CA];
__device__ float g_ffn[L * 1024];
__device__ __half g_bias[134217728];    // [NB*NH][L][L] fp16 = 256 MB

__device__ __forceinline__ float* bufsel(int s) {
    switch (s) {
        case 0: return g_h;
        case 1: return g_h1;
        case 2: return g_q;
        case 3: return g_k;
        case 4: return g_v;
        case 5: return g_o;
        case 6: return g_ffn;
    }
    return nullptr;
}

// ---------------- packed f32x2 helpers (FFMA2) ----------------
typedef unsigned long long f32x2;

__device__ __forceinline__ f32x2 pack2(float lo, float hi) {
    f32x2 r;
    asm("mov.b64 %0, {%1, %2};" : "=l"(r) : "f"(lo), "f"(hi));
    return r;
}
__device__ __forceinline__ void unpack2(f32x2 v, float& a, float& b) {
    asm("mov.b64 {%0, %1}, %2;" : "=f"(a), "=f"(b) : "l"(v));
}
__device__ __forceinline__ void fma2(f32x2& d, f32x2 a, f32x2 b) {
    asm("fma.rn.f32x2 %0, %1, %2, %3;" : "=l"(d) : "l"(a), "l"(b), "l"(d));
}
__device__ __forceinline__ f32x2 f2lo(float4 v) { return pack2(v.x, v.y); }
__device__ __forceinline__ f32x2 f2hi(float4 v) { return pack2(v.z, v.w); }

__device__ __forceinline__ float gelu_exact(float x) {
    return 0.5f * x * (1.0f + erff(x * 0.7071067811865475f));
}

__device__ __forceinline__ unsigned tf32of(float f) {
    unsigned r;
    asm("cvt.rna.tf32.f32 %0, %1;" : "=r"(r) : "f"(f));
    return r;
}

// ---------------- merged setup: consts + time MLP (1 CTA, 1024 threads) ----------------
__global__ void k_setup(const float* __restrict__ sigma,
                        const float* __restrict__ W1, const float* __restrict__ b1,
                        const float* __restrict__ W2, const float* __restrict__ b2) {
    __shared__ float temb[256];
    __shared__ float hid[1024];
    int t = threadIdx.x;
    float s = sigma[0];
    if (t == 0) {
        float s2 = s * s + 256.0f;
        g_consts[0] = rsqrtf(s2);               // c_in
        g_consts[1] = 256.0f / s2;              // c_skip
        g_consts[2] = s * 16.0f * rsqrtf(s2);   // c_out
        g_consts[3] = 0.25f * logf(s + 1e-8f);  // c_noise
    }
    float cn = 0.25f * logf(s + 1e-8f);
    if (t < 256) {
        int j = t & 127;
        float f = expf(-logf(10000.0f) * (float)j / 128.0f);
        float a = cn * f;
        temb[t] = (t < 128) ? cosf(a) : sinf(a);
    }
    __syncthreads();
    {
        const float* w = W1 + (size_t)t * 256;
        float acc = 0.0f;
        #pragma unroll 8
        for (int c = 0; c < 256; c++) acc += temb[c] * w[c];
        hid[t] = gelu_exact(acc + b1[t]);
    }
    __syncthreads();
    if (t < 256) {
        const float* w = W2 + (size_t)t * 1024;
        float acc = 0.0f;
        #pragma unroll 8
        for (int c = 0; c < 1024; c++) acc += hid[c] * w[c];
        g_tc[t] = acc + b2[t];
    }
}

// ada scale/shift: one warp per output row, coalesced weight reads.
__global__ void k_ada(const float* __restrict__ pW1, const float* __restrict__ pb1,
                      const float* __restrict__ pW2, const float* __restrict__ pb2) {
    int wid = threadIdx.x >> 5, lane = threadIdx.x & 31;
    int gid = blockIdx.x * 8 + wid;   // 0..4095
    int blk = gid >> 10;
    int which = (gid >> 9) & 1;
    int idx = gid & 511;
    const float* W = which ? pW2 : pW1;
    const float* pb = which ? pb2 : pb1;
    const float* w = W + ((size_t)blk * 512 + idx) * 256;
    float acc = 0.0f;
    #pragma unroll
    for (int c = lane; c < 256; c += 32) acc += g_tc[c] * w[c];
    #pragma unroll
    for (int off = 16; off > 0; off >>= 1)
        acc += __shfl_xor_sync(0xffffffffu, acc, off);
    if (lane == 0) {
        float val = acc + pb[blk * 512 + idx];
        if (which) g_ss2[blk][idx] = val; else g_ss1[blk][idx] = val;
    }
}

// ---------------- pair bias via tensor cores (tf32 mma.sync) ----------------
// bias[bh][r] = sum_c pair[r][c] * pW[bh][c] : GEMM D[128 rows][32 bh] per CTA.
// m16n8k8 tf32 fragments; conflict-free smem strides (68 words).
__global__ void __launch_bounds__(128) k_pairbias(const float* __restrict__ pair,
                                                  const float* __restrict__ pW) {
    __shared__ __align__(16) char sm[34816 + 8704];  // As | Bs ; Ds aliases As
    unsigned (*As)[68] = (unsigned(*)[68])sm;          // [128][68]
    unsigned (*Bs)[68] = (unsigned(*)[68])(sm + 34816);// [32][68]
    __half   (*Ds)[136] = (__half(*)[136])sm;          // [32][136] aliases As

    size_t r0 = (size_t)blockIdx.x * 128;
    int tid = threadIdx.x, lane = tid & 31, w = tid >> 5;

    // stage A (pair tile 128x64) as tf32, row-major
    const float4* Ap4 = (const float4*)(pair + r0 * 64);
    #pragma unroll
    for (int l = 0; l < 16; l++) {
        int idx = tid + l * 128;            // float4 index 0..2047
        float4 v = Ap4[idx];
        int r = idx >> 4, c4 = (idx & 15) * 4;
        uint4 t4 = make_uint4(tf32of(v.x), tf32of(v.y), tf32of(v.z), tf32of(v.w));
        *(uint4*)&As[r][c4] = t4;
    }
    // stage B (pW 32x64) as tf32
    #pragma unroll
    for (int l = 0; l < 16; l++) {
        int idx = tid + l * 128;
        Bs[idx >> 6][idx & 63] = tf32of(pW[idx]);
    }
    __syncthreads();

    float acc[2][4][4];
    #pragma unroll
    for (int mt = 0; mt < 2; mt++)
        #pragma unroll
        for (int nt = 0; nt < 4; nt++)
            #pragma unroll
            for (int q = 0; q < 4; q++) acc[mt][nt][q] = 0.0f;

    int qr_ = lane >> 2, qc = lane & 3;
    #pragma unroll
    for (int k = 0; k < 8; k++) {
        int kc = k * 8 + qc;
        unsigned b0[4], b1[4];
        #pragma unroll
        for (int nt = 0; nt < 4; nt++) {
            b0[nt] = Bs[nt * 8 + qr_][kc];
            b1[nt] = Bs[nt * 8 + qr_][kc + 4];
        }
        #pragma unroll
        for (int mt = 0; mt < 2; mt++) {
            int mr = w * 32 + mt * 16 + qr_;
            unsigned a0 = As[mr][kc];
            unsigned a1 = As[mr + 8][kc];
            unsigned a2 = As[mr][kc + 4];
            unsigned a3 = As[mr + 8][kc + 4];
            #pragma unroll
            for (int nt = 0; nt < 4; nt++) {
                asm volatile(
                    "mma.sync.aligned.m16n8k8.row.col.f32.tf32.tf32.f32 "
                    "{%0,%1,%2,%3}, {%4,%5,%6,%7}, {%8,%9}, {%0,%1,%2,%3};"
                    : "+f"(acc[mt][nt][0]), "+f"(acc[mt][nt][1]),
                      "+f"(acc[mt][nt][2]), "+f"(acc[mt][nt][3])
                    : "r"(a0), "r"(a1), "r"(a2), "r"(a3),
                      "r"(b0[nt]), "r"(b1[nt]));
            }
        }
    }
    __syncthreads();   // As dead; safe to alias with Ds

    // transpose D into smem: Ds[bh][row]
    #pragma unroll
    for (int mt = 0; mt < 2; mt++) {
        int r = w * 32 + mt * 16 + qr_;
        #pragma unroll
        for (int nt = 0; nt < 4; nt++) {
            int n = nt * 8 + qc * 2;
            Ds[n][r]         = __float2half(acc[mt][nt][0]);
            Ds[n + 1][r]     = __float2half(acc[mt][nt][1]);
            Ds[n][r + 8]     = __float2half(acc[mt][nt][2]);
            Ds[n + 1][r + 8] = __float2half(acc[mt][nt][3]);
        }
    }
    __syncthreads();
    // coalesced fp16 store: 32 planes x 128 halves
    #pragma unroll
    for (int l = 0; l < 16; l++) {
        int idx = tid + l * 128;            // half2 index 0..2047
        int plane = idx >> 6, off = (idx & 63) * 2;
        __half2 hv = __halves2half2(Ds[plane][off], Ds[plane][off + 1]);
        *(__half2*)(g_bias + (size_t)plane * L2 + r0 + off) = hv;
    }
}

// ---------------- generic GEMM: C[M,N] = epi(A[M,K] @ W[N,K]^T) ----------------
// Tile: BM = 32*RP rows x 64 cols, BK=32, 256 threads. Software-pipelined k-loop.
#define EPI_BIAS  1
#define EPI_GELU  2
#define EPI_RES   4
#define EPI_COORD 8

template <int RP, int EPI>
__global__ void __launch_bounds__(256) k_gemm(
                       const float* __restrict__ Aext, int a_sel,
                       const float* __restrict__ Wa, const float* __restrict__ Wb,
                       const float* __restrict__ Wc,
                       const float* __restrict__ bias,
                       int res_sel, int c_sel0, int K, int N,
                       const float* __restrict__ x3,
                       const float* __restrict__ cw3,
                       const float* __restrict__ cb3) {
    const int BM = 32 * RP;
    __shared__ __align__(16) float As[32][BM + 2];
    __shared__ __align__(16) float2 Bs[32][65];   // duplicated (b,b)
    const float* A = (a_sel >= 0) ? bufsel(a_sel) : Aext;
    int z = blockIdx.z;
    const float* W = (z == 0) ? Wa : (z == 1 ? Wb : Wc);
    float* C = bufsel(c_sel0 + z);
    int m0 = blockIdx.y * BM, n0 = blockIdx.x * 64;
    int tid = threadIdx.x, tx = tid & 15, ty = tid >> 4;

    f32x2 acc2[RP][4];
    #pragma unroll
    for (int i = 0; i < RP; i++)
        #pragma unroll
        for (int j = 0; j < 4; j++) acc2[i][j] = 0ULL;

    float av[4 * RP], wv[8];
    // prologue: preload tile kt=0
    #pragma unroll
    for (int l = 0; l < 4 * RP; l++) {
        int idx = tid + l * 256;
        av[l] = A[(size_t)(m0 + (idx >> 5)) * K + (idx & 31)];
    }
    #pragma unroll
    for (int l = 0; l < 8; l++) {
        int idx = tid + l * 256;
        wv[l] = W[(size_t)(n0 + (idx >> 5)) * K + (idx & 31)];
    }

    for (int kt = 0; kt < K; kt += 32) {
        __syncthreads();
        #pragma unroll
        for (int l = 0; l < 4 * RP; l++) {
            int idx = tid + l * 256;
            As[idx & 31][idx >> 5] = av[l];
        }
        #pragma unroll
        for (int l = 0; l < 8; l++) {
            int idx = tid + l * 256;
            Bs[idx & 31][idx >> 5] = make_float2(wv[l], wv[l]);
        }
        __syncthreads();
        // prefetch next tile while computing
        if (kt + 32 < K) {
            int kn = kt + 32;
            #pragma unroll
            for (int l = 0; l < 4 * RP; l++) {
                int idx = tid + l * 256;
                av[l] = A[(size_t)(m0 + (idx >> 5)) * K + kn + (idx & 31)];
            }
            #pragma unroll
            for (int l = 0; l < 8; l++) {
                int idx = tid + l * 256;
                wv[l] = W[(size_t)(n0 + (idx >> 5)) * K + kn + (idx & 31)];
            }
        }
        #pragma unroll 8
        for (int k = 0; k < 32; k++) {
            f32x2 a2[RP];
            #pragma unroll
            for (int ip = 0; ip < RP; ip++)
                a2[ip] = *(const f32x2*)&As[k][ty * 2 * RP + 2 * ip];
            f32x2 bd[4];
            #pragma unroll
            for (int j = 0; j < 4; j++)
                bd[j] = *(const f32x2*)&Bs[k][tx + 16 * j];
            #pragma unroll
            for (int j = 0; j < 4; j++)
                #pragma unroll
                for (int ip = 0; ip < RP; ip++)
                    fma2(acc2[ip][j], a2[ip], bd[j]);
        }
    }
    const float* res = nullptr;
    if (EPI & EPI_RES) res = bufsel(res_sel);
    float cin = (EPI & EPI_COORD) ? g_consts[0] : 0.0f;
    #pragma unroll
    for (int ip = 0; ip < RP; ip++) {
        #pragma unroll
        for (int j = 0; j < 4; j++) {
            float v0, v1;
            unpack2(acc2[ip][j], v0, v1);
            int col = n0 + tx + 16 * j;
            #pragma unroll
            for (int rr = 0; rr < 2; rr++) {
                int row = m0 + ty * 2 * RP + ip * 2 + rr;
                float v = rr ? v1 : v0;
                if (EPI & EPI_BIAS) v += bias[col];
                if (EPI & EPI_COORD) {
                    v += cin * (x3[row * 3 + 0] * cw3[col * 3 + 0] +
                                x3[row * 3 + 1] * cw3[col * 3 + 1] +
                                x3[row * 3 + 2] * cw3[col * 3 + 2]) + cb3[col];
                }
                if (EPI & EPI_GELU) v = gelu_exact(v);
                if (EPI & EPI_RES) v += res[(size_t)row * N + col];
                C[(size_t)row * N + col] = v;
            }
        }
    }
}

// ---------------- adaLN (h -> h1), one block per row ----------------
__global__ void k_adaln(const float* __restrict__ gamma, const float* __restrict__ beta,
                        int b, int which) {
    __shared__ float red[2][8];
    int row = blockIdx.x, t = threadIdx.x;
    int lane = t & 31, wid = t >> 5;
    float x = g_h[(size_t)row * 256 + t];
    float s1 = x, s2 = x * x;
    #pragma unroll
    for (int off = 16; off > 0; off >>= 1) {
        s1 += __shfl_xor_sync(0xffffffffu, s1, off);
        s2 += __shfl_xor_sync(0xffffffffu, s2, off);
    }
    if (lane == 0) { red[0][wid] = s1; red[1][wid] = s2; }
    __syncthreads();
    float S = 0.0f, Q = 0.0f;
    #pragma unroll
    for (int w = 0; w < 8; w++) { S += red[0][w]; Q += red[1][w]; }
    float mu = S * (1.0f / 256.0f);
    float var = Q * (1.0f / 256.0f) - mu * mu;
    float rs = rsqrtf(var + 1e-5f);
    const float* ss = which ? g_ss2[b] : g_ss1[b];
    float scale = ss[t], shift = ss[256 + t];
    g_h1[(size_t)row * 256 + t] =
        ((x - mu) * rs * gamma[t] + beta[t]) * (1.0f + scale) + shift;
}

// ---------------- attention: grid (L/64, NH) = 256 CTAs, 256 threads ----------------
// Phase A: register P (thread = row iA, j = jg+4*jj), exp written in-place to bs.
// Phase B: thread = (row iA, d-slice jg), V loads are 4-way-broadcast LDS128.
// Unnormalized softmax (logits provably small).
__global__ void __launch_bounds__(256) k_attn(int b) {
    __shared__ __align__(16) float qs[64][34];
    __shared__ __align__(16) float ks[64][36];
    __shared__ __align__(16) float vs[64][32];
    __shared__ __align__(16) float bs[64][66];

    int i0 = blockIdx.x * 64, h = blockIdx.y;
    const __half* bias = g_bias + (size_t)(b * NH + h) * L2;
    int tid = threadIdx.x;

    #pragma unroll
    for (int l = 0; l < 8; l++) {
        int idx = tid + l * 256;
        int r = idx >> 5, c = idx & 31;
        qs[r][c] = g_q[(size_t)(i0 + r) * 256 + h * 32 + c];
    }
    __syncthreads();

    int iA = tid >> 2, jg = tid & 3;
    f32x2 qr[16];
    #pragma unroll
    for (int c = 0; c < 16; c++) qr[c] = *(const f32x2*)&qs[iA][2 * c];

    f32x2 o2[4] = {0ULL, 0ULL, 0ULL, 0ULL};
    float lsum = 0.0f;
    const float scale = 0.1767766952966369f;  // 1/sqrt(32)

    for (int jt = 0; jt < 32; jt++) {
        int j0 = jt * 64;
        __syncthreads();
        #pragma unroll
        for (int l = 0; l < 8; l++) {
            int idx = tid + l * 256;
            int r = idx >> 5, c = idx & 31;
            ks[r][c] = g_k[(size_t)(j0 + r) * 256 + h * 32 + c];
            vs[r][c] = g_v[(size_t)(j0 + r) * 256 + h * 32 + c];
        }
        #pragma unroll
        for (int l = 0; l < 8; l++) {
            int idx = tid + l * 256;
            int r = idx >> 5, c2 = idx & 31;
            __half2 hv = *(const __half2*)(bias + (size_t)(i0 + r) * L + j0 + 2 * c2);
            *(float2*)&bs[r][2 * c2] = __half22float2(hv);
        }
        __syncthreads();

        // phase A: s = q.k, p = exp(s*scale + bias), written in place to bs
        #pragma unroll 2
        for (int jj = 0; jj < 16; jj++) {
            int j = jg + 4 * jj;
            f32x2 accA = 0ULL, accB = 0ULL;
            const float4* kp4 = (const float4*)&ks[j][0];
            #pragma unroll
            for (int c = 0; c < 8; c++) {
                float4 kv = kp4[c];
                fma2(accA, qr[2 * c], f2lo(kv));
                fma2(accB, qr[2 * c + 1], f2hi(kv));
            }
            float a0, a1, b0, b1;
            unpack2(accA, a0, a1);
            unpack2(accB, b0, b1);
            float s = (a0 + a1) + (b0 + b1);
            float pv = __expf(s * scale + bs[iA][j]);
            bs[iA][j] = pv;
            lsum += pv;
        }
        __syncthreads();
        // phase B: o += p_j * v_j ; broadcast-friendly LDS128 V loads
        #pragma unroll 4
        for (int j = 0; j < 64; j++) {
            float p = bs[iA][j];
            f32x2 pd = pack2(p, p);
            const float4* vp4 = (const float4*)&vs[j][jg * 8];
            float4 v0 = vp4[0], v1 = vp4[1];
            fma2(o2[0], pd, f2lo(v0));
            fma2(o2[1], pd, f2hi(v0));
            fma2(o2[2], pd, f2lo(v1));
            fma2(o2[3], pd, f2hi(v1));
        }
    }
    // quad-reduce lsum (lanes jg=0..3 share row iA)
    lsum += __shfl_xor_sync(0xffffffffu, lsum, 1);
    lsum += __shfl_xor_sync(0xffffffffu, lsum, 2);
    float inv = 1.0f / lsum;
    float* op = g_o + (size_t)(i0 + iA) * 256 + h * 32 + jg * 8;
    #pragma unroll
    for (int q = 0; q < 4; q++) {
        float lo, hi;
        unpack2(o2[q], lo, hi);
        *(float2*)(op + 2 * q) = make_float2(lo * inv, hi * inv);
    }
}

// ---------------- final projection ----------------
__global__ void k_final(const float* __restrict__ x, const float* __restrict__ oW,
                        const float* __restrict__ ob, float* __restrict__ out) {
    int row = blockIdx.x;
    int w = threadIdx.x >> 5, lane = threadIdx.x & 31;
    const float* hr = g_h + (size_t)row * 256;
    const float* wr = oW + w * 256;
    float acc = 0.0f;
    #pragma unroll
    for (int c = lane; c < 256; c += 32) acc += hr[c] * wr[c];
    #pragma unroll
    for (int off = 16; off > 0; off >>= 1)
        acc += __shfl_down_sync(0xffffffffu, acc, off);
    if (lane == 0)
        out[row * 3 + w] = g_consts[1] * x[row * 3 + w] + g_consts[2] * (acc + ob[w]);
}

// ---------------- host launcher ----------------
extern "C" void kernel_launch(void* const* d_in, const int* in_sizes, int n_in,
                              void* d_out, int out_size) {
    const float* x_noisy  = (const float*)d_in[0];
    const float* sigma    = (const float*)d_in[1];
    const float* single   = (const float*)d_in[2];
    const float* pair     = (const float*)d_in[3];
    const float* coord_W  = (const float*)d_in[4];
    const float* coord_b  = (const float*)d_in[5];
    const float* single_W = (const float*)d_in[6];
    const float* single_b = (const float*)d_in[7];
    const float* tmlp_W1  = (const float*)d_in[8];
    const float* tmlp_b1  = (const float*)d_in[9];
    const float* tmlp_W2  = (const float*)d_in[10];
    const float* tmlp_b2  = (const float*)d_in[11];
    const float* ada1_g   = (const float*)d_in[12];
    const float* ada1_b   = (const float*)d_in[13];
    const float* ada1_pW  = (const float*)d_in[14];
    const float* ada1_pb  = (const float*)d_in[15];
    const float* qW       = (const float*)d_in[16];
    const float* kW       = (const float*)d_in[17];
    const float* vW       = (const float*)d_in[18];
    const float* pairW    = (const float*)d_in[19];
    const float* outW     = (const float*)d_in[20];
    const float* outb     = (const float*)d_in[21];
    const float* ada2_g   = (const float*)d_in[22];
    const float* ada2_b   = (const float*)d_in[23];
    const float* ada2_pW  = (const float*)d_in[24];
    const float* ada2_pb  = (const float*)d_in[25];
    const float* ffn_W1   = (const float*)d_in[26];
    const float* ffn_b1   = (const float*)d_in[27];
    const float* ffn_W2   = (const float*)d_in[28];
    const float* ffn_b2   = (const float*)d_in[29];
    const float* out_W    = (const float*)d_in[30];
    const float* out_b    = (const float*)d_in[31];
    float* out = (float*)d_out;

    k_setup<<<1, 1024>>>(sigma, tmlp_W1, tmlp_b1, tmlp_W2, tmlp_b2);   // 0
    k_ada<<<512, 256>>>(ada1_pW, ada1_pb, ada2_pW, ada2_pb);           // 1
    k_gemm<2, EPI_BIAS | EPI_COORD><<<dim3(4, 32, 1), 256>>>(          // 2
        single, -1, single_W, single_W, single_W, single_b, -1, 0, 256, 256,
        x_noisy, coord_W, coord_b);
    k_pairbias<<<(int)(L2 / 128), 128>>>(pair, pairW);                 // 3 <- profiled

    for (int b = 0; b < NB; b++) {
        k_adaln<<<L, 256>>>(ada1_g + b * 256, ada1_b + b * 256, b, 0);
        k_gemm<4, 0><<<dim3(4, 16, 3), 256>>>(
            nullptr, 1, qW + (size_t)b * 65536, kW + (size_t)b * 65536,
            vW + (size_t)b * 65536, nullptr, -1, 2, 256, 256,
            nullptr, nullptr, nullptr);
        k_attn<<<dim3(32, 8), 256>>>(b);
        k_gemm<2, EPI_BIAS | EPI_RES><<<dim3(4, 32, 1), 256>>>(
            nullptr, 5, outW + (size_t)b * 65536, outW, outW, outb + b * 256,
            0, 0, 256, 256, nullptr, nullptr, nullptr);
        k_adaln<<<L, 256>>>(ada2_g + b * 256, ada2_b + b * 256, b, 1);
        k_gemm<4, EPI_BIAS | EPI_GELU><<<dim3(16, 16, 1), 256>>>(
            nullptr, 1, ffn_W1 + (size_t)b * 262144, ffn_W1, ffn_W1,
            ffn_b1 + b * 1024, -1, 6, 256, 1024, nullptr, nullptr, nullptr);
        k_gemm<2, EPI_BIAS | EPI_RES><<<dim3(4, 32, 1), 256>>>(
            nullptr, 6, ffn_W2 + (size_t)b * 262144, ffn_W2, ffn_W2,
            ffn_b2 + b * 256, 0, 0, 1024, 256, nullptr, nullptr, nullptr);
    }
    k_final<<<L, 96>>>(x_noisy, out_W, out_b, out);
}